// round 7
// baseline (speedup 1.0000x reference)
#include <cuda_runtime.h>
#include <cuda_bf16.h>
#include <math.h>

// Problem constants
#define BATCH   4
#define SEQ     2048
#define DMODEL  1024
#define NHEAD   16
#define DHEAD   64
#define MROWS   (BATCH * SEQ)          // 8192
#define N_QKV   (3 * DMODEL)           // 3072
#define ATT_SCALE 0.125f               // 64^-0.5 (exact power of two)

// ---------------------------------------------------------------------------
// Device scratch (allocation-free rule: __device__ globals)
// ---------------------------------------------------------------------------
__device__ float g_qkv[(size_t)MROWS * N_QKV];                 // 96 MB
__device__ float g_q[(size_t)BATCH * NHEAD * SEQ * DHEAD];     // 32 MB
__device__ float g_k[(size_t)BATCH * NHEAD * SEQ * DHEAD];     // 32 MB
__device__ float g_v[(size_t)BATCH * NHEAD * SEQ * DHEAD];     // 32 MB
__device__ float g_ctx[(size_t)MROWS * DMODEL];                // 32 MB

__device__ __forceinline__ unsigned f2tf32(float f) {
    unsigned u;
    asm("cvt.rna.tf32.f32 %0, %1;" : "=r"(u) : "f"(f));
    return u;
}
__device__ __forceinline__ void mma_tf32(float* c, const unsigned* a,
                                         unsigned b0, unsigned b1) {
    asm("mma.sync.aligned.m16n8k8.row.col.f32.tf32.tf32.f32 "
        "{%0,%1,%2,%3}, {%4,%5,%6,%7}, {%8,%9}, {%0,%1,%2,%3};"
        : "+f"(c[0]), "+f"(c[1]), "+f"(c[2]), "+f"(c[3])
        : "r"(a[0]), "r"(a[1]), "r"(a[2]), "r"(a[3]), "r"(b0), "r"(b1));
}
__device__ __forceinline__ void cpa16(unsigned dst, const void* src) {
    asm volatile("cp.async.cg.shared.global [%0], [%1], 16;" :: "r"(dst), "l"(src));
}
#define CP_COMMIT()  asm volatile("cp.async.commit_group;")
#define CP_WAIT(n)   asm volatile("cp.async.wait_group %0;" :: "n"(n))

// ---------------------------------------------------------------------------
// TF32 tensor-core GEMM (NT) with 3-stage cp.async pipeline.
// C[m,n] = sum_k A[m,k]*B[n,k] + bias[n]. Raw fp32 bits fed to tf32 MMA.
// Block tile 128x128, BK=32, 256 threads (8 warps), warp tile 32x64.
// ---------------------------------------------------------------------------
#define TBM 128
#define TBN 128
#define TBK 32
#define SMP 36                         // padded row stride (words)
#define GSTG 3
#define GSTW (TBM * SMP * 2)           // words per stage (A + B panels)

__global__ __launch_bounds__(256, 1)
void tf32gemm_nt_bias(const float* __restrict__ A, const float* __restrict__ B,
                      const float* __restrict__ bias, float* __restrict__ C,
                      int M, int N, int K)
{
    extern __shared__ unsigned smg[];
    const unsigned sbase = (unsigned)__cvta_generic_to_shared(smg);

    const int tid  = threadIdx.x;
    const int lane = tid & 31;
    const int wid  = tid >> 5;
    const int wm   = wid >> 1;
    const int wn   = wid & 1;
    const int g    = lane >> 2;
    const int t    = lane & 3;

    const int bm = blockIdx.y * TBM;
    const int bn = blockIdx.x * TBN;
    const int nk = K / TBK;

    float acc[2][8][4];
#pragma unroll
    for (int mt = 0; mt < 2; mt++)
#pragma unroll
        for (int nt = 0; nt < 8; nt++)
#pragma unroll
            for (int r = 0; r < 4; r++) acc[mt][nt][r] = 0.f;

    // ---- stage issue: 8 cp.async (16B) per thread
    auto issue = [&](int i) {
        unsigned base = (unsigned)((i % GSTG) * GSTW);
#pragma unroll
        for (int it = 0; it < 4; it++) {
            int slot = tid + 256 * it;
            int row  = slot >> 3;
            int kv   = (slot & 7) * 4;
            cpa16(sbase + (base + row * SMP + kv) * 4,
                  A + (size_t)(bm + row) * K + i * TBK + kv);
            cpa16(sbase + (base + TBM * SMP + row * SMP + kv) * 4,
                  B + (size_t)(bn + row) * K + i * TBK + kv);
        }
    };

    issue(0); CP_COMMIT();
    issue(1); CP_COMMIT();

    for (int i = 0; i < nk; i++) {
        if (i + 2 < nk) issue(i + 2);
        CP_COMMIT();
        CP_WAIT(2);
        __syncthreads();

        const unsigned* As = smg + (i % GSTG) * GSTW;
        const unsigned* Bs = As + TBM * SMP;
#pragma unroll
        for (int kk = 0; kk < TBK; kk += 8) {
            unsigned af[2][4], bf[8][2];
#pragma unroll
            for (int mt = 0; mt < 2; mt++) {
                int m0 = wm * 32 + mt * 16;
                af[mt][0] = As[(m0 + g)     * SMP + kk + t];
                af[mt][1] = As[(m0 + g + 8) * SMP + kk + t];
                af[mt][2] = As[(m0 + g)     * SMP + kk + t + 4];
                af[mt][3] = As[(m0 + g + 8) * SMP + kk + t + 4];
            }
#pragma unroll
            for (int nt = 0; nt < 8; nt++) {
                int n0 = wn * 64 + nt * 8;
                bf[nt][0] = Bs[(n0 + g) * SMP + kk + t];
                bf[nt][1] = Bs[(n0 + g) * SMP + kk + t + 4];
            }
#pragma unroll
            for (int mt = 0; mt < 2; mt++)
#pragma unroll
                for (int nt = 0; nt < 8; nt++)
                    mma_tf32(acc[mt][nt], af[mt], bf[nt][0], bf[nt][1]);
        }
        __syncthreads();
    }

#pragma unroll
    for (int mt = 0; mt < 2; mt++) {
        int row0 = bm + wm * 32 + mt * 16 + g;
#pragma unroll
        for (int nt = 0; nt < 8; nt++) {
            int col = bn + wn * 64 + nt * 8 + 2 * t;
            float bx = bias[col], by = bias[col + 1];
            float2 r0 = make_float2(acc[mt][nt][0] + bx, acc[mt][nt][1] + by);
            float2 r1 = make_float2(acc[mt][nt][2] + bx, acc[mt][nt][3] + by);
            *(float2*)(C + (size_t)row0 * N + col)       = r0;
            *(float2*)(C + (size_t)(row0 + 8) * N + col) = r1;
        }
    }
}

// ---------------------------------------------------------------------------
// RoPE + split: qkv[M, 3072] -> q,k (roped), v in [B,H,S,Dh] layout.
// ---------------------------------------------------------------------------
__global__ void rope_split_kernel(const float* __restrict__ qkv,
                                  const int* __restrict__ p,
                                  float* __restrict__ q,
                                  float* __restrict__ k,
                                  float* __restrict__ v)
{
    int t = blockIdx.x * blockDim.x + threadIdx.x;
    const int total = BATCH * NHEAD * SEQ * 32;
    if (t >= total) return;
    int i = t & 31;
    int s = (t >> 5) & (SEQ - 1);
    int h = (t >> 16) & (NHEAD - 1);
    int b = t >> 20;

    int m = b * SEQ + s;
    const float* row = qkv + (size_t)m * N_QKV;
    int col = h * DHEAD + i;
    float qa = row[col],            qb = row[col + 32];
    float ka = row[DMODEL + col],   kb = row[DMODEL + col + 32];
    float va = row[2*DMODEL + col], vb = row[2*DMODEL + col + 32];

    float pos = (float)p[m];
    float f = (float)exp2(-(double)i * (13.287712379549449 / 32.0)); // log2(10000)
    float ang = pos * f;
    float sn, cs;
    sincosf(ang, &sn, &cs);

    size_t o = ((size_t)(b * NHEAD + h) * SEQ + s) * DHEAD + i;
    q[o]      = qa * cs + qb * sn;
    q[o + 32] = qb * cs - qa * sn;
    k[o]      = ka * cs + kb * sn;
    k[o + 32] = kb * cs - ka * sn;
    v[o]      = va;
    v[o + 32] = vb;
}

// ---------------------------------------------------------------------------
// Tensor-core flash attention (tf32 mma.m16n8k8) + 2-stage cp.async K/V.
// Block: 256 threads / 8 warps. TQ=128, TK=64. Q pre-scaled (rna tf32);
// K/V consumed as raw fp32 bits (tf32 truncation).
// ---------------------------------------------------------------------------
#define FTQ 128
#define FTK 64
#define KSTR 68
#define VSTR 72
#define FSTW (FTK * KSTR + FTK * VSTR)   // 8960 words per stage

__global__ __launch_bounds__(256, 1)
void flash_attn_tc_kernel(const float* __restrict__ Q, const float* __restrict__ K,
                          const float* __restrict__ V, float* __restrict__ ctx)
{
    extern __shared__ unsigned smf[];
    const unsigned sbase = (unsigned)__cvta_generic_to_shared(smf);

    const int tid  = threadIdx.x;
    const int lane = tid & 31;
    const int wid  = tid >> 5;         // 0..7 -> q-row tile
    const int g    = lane >> 2;        // 0..7
    const int t    = lane & 3;         // 0..3

    const int bh = blockIdx.y;
    const int b = bh >> 4, h = bh & 15;
    const int s0 = blockIdx.x * FTQ;

    const float* qbase = Q + (size_t)bh * SEQ * DHEAD;
    const float* kbase = K + (size_t)bh * SEQ * DHEAD;
    const float* vbase = V + (size_t)bh * SEQ * DHEAD;

    // --- Stage Q tile [128][64] (scaled, rna tf32) across stage0+stage1 area.
#pragma unroll
    for (int it = 0; it < 8; it++) {
        int slot = tid + 256 * it;       // 0..2047
        int row  = slot >> 4;
        int c4   = (slot & 15) * 4;
        float4 qv = *(const float4*)(qbase + (size_t)(s0 + row) * DHEAD + c4);
        uint4 uq = make_uint4(f2tf32(qv.x * ATT_SCALE), f2tf32(qv.y * ATT_SCALE),
                              f2tf32(qv.z * ATT_SCALE), f2tf32(qv.w * ATT_SCALE));
        *(uint4*)&smf[row * KSTR + c4] = uq;
    }
    __syncthreads();

    unsigned qf[8][4];
    {
        int r0 = wid * 16 + g;
#pragma unroll
        for (int kk = 0; kk < 8; kk++) {
            qf[kk][0] = smf[(r0)     * KSTR + kk * 8 + t];
            qf[kk][1] = smf[(r0 + 8) * KSTR + kk * 8 + t];
            qf[kk][2] = smf[(r0)     * KSTR + kk * 8 + t + 4];
            qf[kk][3] = smf[(r0 + 8) * KSTR + kk * 8 + t + 4];
        }
    }
    __syncthreads();

    auto issueKV = [&](int kt) {
        unsigned base = (unsigned)((kt & 1) * FSTW);
#pragma unroll
        for (int it = 0; it < 4; it++) {
            int slot = tid + 256 * it;     // 0..1023
            int row  = slot >> 4;
            int c4   = (slot & 15) * 4;
            cpa16(sbase + (base + row * KSTR + c4) * 4,
                  kbase + (size_t)(kt * FTK + row) * DHEAD + c4);
            cpa16(sbase + (base + FTK * KSTR + row * VSTR + c4) * 4,
                  vbase + (size_t)(kt * FTK + row) * DHEAD + c4);
        }
    };

    float oacc[8][4];
#pragma unroll
    for (int nt = 0; nt < 8; nt++)
#pragma unroll
        for (int r = 0; r < 4; r++) oacc[nt][r] = 0.f;

    float m0 = -1e30f, m1 = -1e30f, l0 = 0.f, l1 = 0.f;

    const unsigned FULL = 0xffffffffu;
    const int srcA = (lane & ~3) | (t >> 1);
    const int srcB = srcA + 2;
    const int NKT = SEQ / FTK;

    issueKV(0); CP_COMMIT();

    for (int kt = 0; kt < NKT; kt++) {
        if (kt + 1 < NKT) issueKV(kt + 1);
        CP_COMMIT();
        CP_WAIT(1);
        __syncthreads();

        const unsigned* Ks = smf + (kt & 1) * FSTW;
        const unsigned* Vs = Ks + FTK * KSTR;

        // ---- S = Q K^T (scaled)
        float s[8][4];
#pragma unroll
        for (int nt = 0; nt < 8; nt++)
#pragma unroll
            for (int r = 0; r < 4; r++) s[nt][r] = 0.f;

#pragma unroll
        for (int kk = 0; kk < 8; kk++) {
#pragma unroll
            for (int nt = 0; nt < 8; nt++) {
                unsigned b0 = Ks[(nt * 8 + g) * KSTR + kk * 8 + t];
                unsigned b1 = Ks[(nt * 8 + g) * KSTR + kk * 8 + t + 4];
                mma_tf32(s[nt], qf[kk], b0, b1);
            }
        }

        // ---- online softmax on fragments
        float tm0 = -1e30f, tm1 = -1e30f;
#pragma unroll
        for (int nt = 0; nt < 8; nt++) {
            tm0 = fmaxf(tm0, fmaxf(s[nt][0], s[nt][1]));
            tm1 = fmaxf(tm1, fmaxf(s[nt][2], s[nt][3]));
        }
        tm0 = fmaxf(tm0, __shfl_xor_sync(FULL, tm0, 1));
        tm0 = fmaxf(tm0, __shfl_xor_sync(FULL, tm0, 2));
        tm1 = fmaxf(tm1, __shfl_xor_sync(FULL, tm1, 1));
        tm1 = fmaxf(tm1, __shfl_xor_sync(FULL, tm1, 2));

        float mn0 = fmaxf(m0, tm0), mn1 = fmaxf(m1, tm1);
        float corr0 = __expf(m0 - mn0), corr1 = __expf(m1 - mn1);
        m0 = mn0; m1 = mn1;

        float sum0 = 0.f, sum1 = 0.f;
#pragma unroll
        for (int nt = 0; nt < 8; nt++) {
            s[nt][0] = __expf(s[nt][0] - mn0);
            s[nt][1] = __expf(s[nt][1] - mn0);
            s[nt][2] = __expf(s[nt][2] - mn1);
            s[nt][3] = __expf(s[nt][3] - mn1);
            sum0 += s[nt][0] + s[nt][1];
            sum1 += s[nt][2] + s[nt][3];
        }
        sum0 += __shfl_xor_sync(FULL, sum0, 1);
        sum0 += __shfl_xor_sync(FULL, sum0, 2);
        sum1 += __shfl_xor_sync(FULL, sum1, 1);
        sum1 += __shfl_xor_sync(FULL, sum1, 2);
        l0 = l0 * corr0 + sum0;
        l1 = l1 * corr1 + sum1;

#pragma unroll
        for (int nt = 0; nt < 8; nt++) {
            oacc[nt][0] *= corr0; oacc[nt][1] *= corr0;
            oacc[nt][2] *= corr1; oacc[nt][3] *= corr1;
        }

        // ---- O += P V : A frag built from s via shfl (no smem round trip)
#pragma unroll
        for (int kk = 0; kk < 8; kk++) {
            float e, o_;
            e  = __shfl_sync(FULL, s[kk][0], srcA);
            o_ = __shfl_sync(FULL, s[kk][1], srcA);
            float p0 = (t & 1) ? o_ : e;
            e  = __shfl_sync(FULL, s[kk][2], srcA);
            o_ = __shfl_sync(FULL, s[kk][3], srcA);
            float p1 = (t & 1) ? o_ : e;
            e  = __shfl_sync(FULL, s[kk][0], srcB);
            o_ = __shfl_sync(FULL, s[kk][1], srcB);
            float p2 = (t & 1) ? o_ : e;
            e  = __shfl_sync(FULL, s[kk][2], srcB);
            o_ = __shfl_sync(FULL, s[kk][3], srcB);
            float p3 = (t & 1) ? o_ : e;
            unsigned pa[4] = {f2tf32(p0), f2tf32(p1), f2tf32(p2), f2tf32(p3)};
#pragma unroll
            for (int nt = 0; nt < 8; nt++) {
                unsigned b0 = Vs[(kk * 8 + t)     * VSTR + nt * 8 + g];
                unsigned b1 = Vs[(kk * 8 + t + 4) * VSTR + nt * 8 + g];
                mma_tf32(oacc[nt], pa, b0, b1);
            }
        }
        __syncthreads();
    }

    // ---- epilogue: normalize, write ctx[b][s][h*64+d]
    float inv0 = 1.f / l0, inv1 = 1.f / l1;
    int r0 = s0 + wid * 16 + g;
#pragma unroll
    for (int nt = 0; nt < 8; nt++) {
        int col = h * DHEAD + nt * 8 + 2 * t;
        float2 w0 = make_float2(oacc[nt][0] * inv0, oacc[nt][1] * inv0);
        float2 w1 = make_float2(oacc[nt][2] * inv1, oacc[nt][3] * inv1);
        *(float2*)(ctx + (size_t)(b * SEQ + r0) * DMODEL + col)     = w0;
        *(float2*)(ctx + (size_t)(b * SEQ + r0 + 8) * DMODEL + col) = w1;
    }
}

// ---------------------------------------------------------------------------
// Launch
// ---------------------------------------------------------------------------
extern "C" void kernel_launch(void* const* d_in, const int* in_sizes, int n_in,
                              void* d_out, int out_size)
{
    (void)in_sizes; (void)n_in; (void)out_size;
    const float* x      = (const float*)d_in[0];   // [4,2048,1024]
    const int*   p      = (const int*)  d_in[1];   // [4,2048]
    const float* Wqkv_w = (const float*)d_in[2];   // [3072,1024]
    const float* Wqkv_b = (const float*)d_in[3];   // [3072]
    const float* Wo_w   = (const float*)d_in[4];   // [1024,1024]
    const float* Wo_b   = (const float*)d_in[5];   // [1024]
    float* out = (float*)d_out;                    // [4,2048,1024]

    float *qkv, *q, *k, *v, *ctx;
    cudaGetSymbolAddress((void**)&qkv, g_qkv);
    cudaGetSymbolAddress((void**)&q,   g_q);
    cudaGetSymbolAddress((void**)&k,   g_k);
    cudaGetSymbolAddress((void**)&v,   g_v);
    cudaGetSymbolAddress((void**)&ctx, g_ctx);

    const int gemm_smem  = GSTG * GSTW * 4;   // 110592 B
    const int flash_smem = 2 * FSTW * 4;      //  71680 B
    cudaFuncSetAttribute(tf32gemm_nt_bias,
                         cudaFuncAttributeMaxDynamicSharedMemorySize, gemm_smem);
    cudaFuncSetAttribute(flash_attn_tc_kernel,
                         cudaFuncAttributeMaxDynamicSharedMemorySize, flash_smem);

    // 1) QKV projection (tf32 tensor cores, cp.async pipeline)
    {
        dim3 grid(N_QKV / TBN, MROWS / TBM);
        tf32gemm_nt_bias<<<grid, 256, gemm_smem>>>(x, Wqkv_w, Wqkv_b, qkv,
                                                   MROWS, N_QKV, DMODEL);
    }
    // 2) RoPE + split into [B,H,S,Dh]
    {
        int total = BATCH * NHEAD * SEQ * 32;
        rope_split_kernel<<<(total + 255) / 256, 256>>>(qkv, p, q, k, v);
    }
    // 3) Tensor-core flash attention -> ctx in [B,S,D]
    {
        dim3 grid(SEQ / FTQ, BATCH * NHEAD);
        flash_attn_tc_kernel<<<grid, 256, flash_smem>>>(q, k, v, ctx);
    }
    // 4) Output projection (tf32 tensor cores, cp.async pipeline)
    {
        dim3 grid(DMODEL / TBN, MROWS / TBM);
        tf32gemm_nt_bias<<<grid, 256, gemm_smem>>>(ctx, Wo_w, Wo_b, out,
                                                   MROWS, DMODEL, DMODEL);
    }
}

// round 8
// speedup vs baseline: 1.3409x; 1.3409x over previous
#include <cuda_runtime.h>
#include <cuda_bf16.h>
#include <math.h>

// Problem constants
#define BATCH   4
#define SEQ     2048
#define DMODEL  1024
#define NHEAD   16
#define DHEAD   64
#define MROWS   (BATCH * SEQ)          // 8192
#define N_QKV   (3 * DMODEL)           // 3072
#define ATT_SCALE 0.125f               // 64^-0.5 (exact power of two)

// ---------------------------------------------------------------------------
// Device scratch (allocation-free rule: __device__ globals)
// ---------------------------------------------------------------------------
__device__ float g_qkv[(size_t)MROWS * N_QKV];                 // 96 MB
__device__ float g_q[(size_t)BATCH * NHEAD * SEQ * DHEAD];     // 32 MB
__device__ float g_k[(size_t)BATCH * NHEAD * SEQ * DHEAD];     // 32 MB
__device__ float g_v[(size_t)BATCH * NHEAD * SEQ * DHEAD];     // 32 MB
__device__ float g_ctx[(size_t)MROWS * DMODEL];                // 32 MB

__device__ __forceinline__ unsigned f2tf32(float f) {
    unsigned u;
    asm("cvt.rna.tf32.f32 %0, %1;" : "=r"(u) : "f"(f));
    return u;
}
__device__ __forceinline__ void mma_tf32(float* c, const unsigned* a,
                                         unsigned b0, unsigned b1) {
    asm("mma.sync.aligned.m16n8k8.row.col.f32.tf32.tf32.f32 "
        "{%0,%1,%2,%3}, {%4,%5,%6,%7}, {%8,%9}, {%0,%1,%2,%3};"
        : "+f"(c[0]), "+f"(c[1]), "+f"(c[2]), "+f"(c[3])
        : "r"(a[0]), "r"(a[1]), "r"(a[2]), "r"(a[3]), "r"(b0), "r"(b1));
}

// ---------------------------------------------------------------------------
// TF32 tensor-core GEMM v3 (NT): C[m,n] = sum_k A[m,k]*B[n,k] + bias[n]
// Block tile 256x128, BK=16, 256 threads / 8 warps, warp tile 64x64
// (4 x m16, 8 x n8). Double-buffered smem + register-staged LDG prefetch,
// one __syncthreads per K-iter. rna tf32 conversion in registers.
// ---------------------------------------------------------------------------
#define TBM 256
#define TBN 128
#define TBK 16
#define SMPW 20                          // padded row stride (words)
#define GBUFW ((TBM + TBN) * SMPW)       // 7680 words per buffer

__global__ __launch_bounds__(256, 1)
void tf32gemm_v3(const float* __restrict__ A, const float* __restrict__ B,
                 const float* __restrict__ bias, float* __restrict__ C,
                 int M, int N, int K)
{
    extern __shared__ unsigned sm3[];

    const int tid  = threadIdx.x;
    const int lane = tid & 31;
    const int wid  = tid >> 5;
    const int wm   = wid >> 1;           // 0..3 -> 64 rows
    const int wn   = wid & 1;            // 0..1 -> 64 cols
    const int g    = lane >> 2;          // 0..7
    const int t    = lane & 3;           // 0..3

    const int bm = blockIdx.y * TBM;
    const int bn = blockIdx.x * TBN;
    const int nk = K / TBK;

    const int ldr = tid >> 2;            // loader row  (0..63 per chunk)
    const int ldc = (tid & 3) * 4;       // loader col4

    float acc[4][8][4];
#pragma unroll
    for (int mt = 0; mt < 4; mt++)
#pragma unroll
        for (int nt = 0; nt < 8; nt++)
#pragma unroll
            for (int r = 0; r < 4; r++) acc[mt][nt][r] = 0.f;

    float4 stA[4], stB[2];
    auto ldg = [&](int i) {
#pragma unroll
        for (int it = 0; it < 4; it++) {
            int row = ldr + 64 * it;     // 0..255
            stA[it] = *(const float4*)(A + (size_t)(bm + row) * K + i * TBK + ldc);
        }
#pragma unroll
        for (int it = 0; it < 2; it++) {
            int row = ldr + 64 * it;     // 0..127
            stB[it] = *(const float4*)(B + (size_t)(bn + row) * K + i * TBK + ldc);
        }
    };
    auto sts = [&](int i) {
        unsigned* s = sm3 + (i & 1) * GBUFW;
#pragma unroll
        for (int it = 0; it < 4; it++) {
            int row = ldr + 64 * it;
            *(uint4*)&s[row * SMPW + ldc] =
                make_uint4(f2tf32(stA[it].x), f2tf32(stA[it].y),
                           f2tf32(stA[it].z), f2tf32(stA[it].w));
        }
#pragma unroll
        for (int it = 0; it < 2; it++) {
            int row = ldr + 64 * it;
            *(uint4*)&s[TBM * SMPW + row * SMPW + ldc] =
                make_uint4(f2tf32(stB[it].x), f2tf32(stB[it].y),
                           f2tf32(stB[it].z), f2tf32(stB[it].w));
        }
    };

    ldg(0); sts(0);
    __syncthreads();

    for (int i = 0; i < nk; i++) {
        if (i + 1 < nk) ldg(i + 1);

        const unsigned* As = sm3 + (i & 1) * GBUFW;
        const unsigned* Bs = As + TBM * SMPW;
#pragma unroll
        for (int kk = 0; kk < TBK; kk += 8) {
            unsigned af[4][4], bf[8][2];
#pragma unroll
            for (int mt = 0; mt < 4; mt++) {
                int m0 = wm * 64 + mt * 16;
                af[mt][0] = As[(m0 + g)     * SMPW + kk + t];
                af[mt][1] = As[(m0 + g + 8) * SMPW + kk + t];
                af[mt][2] = As[(m0 + g)     * SMPW + kk + t + 4];
                af[mt][3] = As[(m0 + g + 8) * SMPW + kk + t + 4];
            }
#pragma unroll
            for (int nt = 0; nt < 8; nt++) {
                int n0 = wn * 64 + nt * 8;
                bf[nt][0] = Bs[(n0 + g) * SMPW + kk + t];
                bf[nt][1] = Bs[(n0 + g) * SMPW + kk + t + 4];
            }
#pragma unroll
            for (int mt = 0; mt < 4; mt++)
#pragma unroll
                for (int nt = 0; nt < 8; nt++)
                    mma_tf32(acc[mt][nt], af[mt], bf[nt][0], bf[nt][1]);
        }

        if (i + 1 < nk) sts(i + 1);
        __syncthreads();
    }

    // Epilogue: bias + float2 stores.
#pragma unroll
    for (int mt = 0; mt < 4; mt++) {
        int row0 = bm + wm * 64 + mt * 16 + g;
#pragma unroll
        for (int nt = 0; nt < 8; nt++) {
            int col = bn + wn * 64 + nt * 8 + 2 * t;
            float bx = bias[col], by = bias[col + 1];
            float2 r0 = make_float2(acc[mt][nt][0] + bx, acc[mt][nt][1] + by);
            float2 r1 = make_float2(acc[mt][nt][2] + bx, acc[mt][nt][3] + by);
            *(float2*)(C + (size_t)row0 * N + col)       = r0;
            *(float2*)(C + (size_t)(row0 + 8) * N + col) = r1;
        }
    }
}

// ---------------------------------------------------------------------------
// RoPE + split: qkv[M, 3072] -> q,k (roped), v in [B,H,S,Dh] layout.
// ---------------------------------------------------------------------------
__global__ void rope_split_kernel(const float* __restrict__ qkv,
                                  const int* __restrict__ p,
                                  float* __restrict__ q,
                                  float* __restrict__ k,
                                  float* __restrict__ v)
{
    int t = blockIdx.x * blockDim.x + threadIdx.x;
    const int total = BATCH * NHEAD * SEQ * 32;
    if (t >= total) return;
    int i = t & 31;
    int s = (t >> 5) & (SEQ - 1);
    int h = (t >> 16) & (NHEAD - 1);
    int b = t >> 20;

    int m = b * SEQ + s;
    const float* row = qkv + (size_t)m * N_QKV;
    int col = h * DHEAD + i;
    float qa = row[col],            qb = row[col + 32];
    float ka = row[DMODEL + col],   kb = row[DMODEL + col + 32];
    float va = row[2*DMODEL + col], vb = row[2*DMODEL + col + 32];

    float pos = (float)p[m];
    float f = (float)exp2(-(double)i * (13.287712379549449 / 32.0)); // log2(10000)
    float ang = pos * f;
    float sn, cs;
    sincosf(ang, &sn, &cs);

    size_t o = ((size_t)(b * NHEAD + h) * SEQ + s) * DHEAD + i;
    q[o]      = qa * cs + qb * sn;
    q[o + 32] = qb * cs - qa * sn;
    k[o]      = ka * cs + kb * sn;
    k[o + 32] = kb * cs - ka * sn;
    v[o]      = va;
    v[o + 32] = vb;
}

// ---------------------------------------------------------------------------
// Tensor-core flash attention (tf32 mma.m16n8k8) — R5 known-good version.
// Block: 256 threads / 8 warps. TQ=128, TK=64. Q pre-scaled, rna tf32.
// K smem stride 68, V stride 72 (conflict-free fragment LDS).
// P->A-operand layout fix via shfl (no smem round trip).
// ---------------------------------------------------------------------------
#define FTQ 128
#define FTK 64
#define KSTR 68
#define VSTR 72

__global__ __launch_bounds__(256, 1)
void flash_attn_tc_kernel(const float* __restrict__ Q, const float* __restrict__ K,
                          const float* __restrict__ V, float* __restrict__ ctx)
{
    __shared__ __align__(16) unsigned sm[FTK * KSTR + FTK * VSTR]; // 35840 B
    unsigned* Ks = sm;
    unsigned* Vs = sm + FTK * KSTR;

    const int tid  = threadIdx.x;
    const int lane = tid & 31;
    const int wid  = tid >> 5;         // 0..7 -> q-row tile
    const int g    = lane >> 2;        // 0..7
    const int t    = lane & 3;         // 0..3

    const int bh = blockIdx.y;
    const int b = bh >> 4, h = bh & 15;
    const int s0 = blockIdx.x * FTQ;

    const float* qbase = Q + (size_t)bh * SEQ * DHEAD;
    const float* kbase = K + (size_t)bh * SEQ * DHEAD;
    const float* vbase = V + (size_t)bh * SEQ * DHEAD;

    // --- Stage Q tile [128][64] into smem (scaled, tf32), then build A frags.
#pragma unroll
    for (int it = 0; it < 8; it++) {
        int slot = tid + 256 * it;       // 0..2047
        int row  = slot >> 4;
        int c4   = (slot & 15) * 4;
        float4 qv = *(const float4*)(qbase + (size_t)(s0 + row) * DHEAD + c4);
        uint4 uq = make_uint4(f2tf32(qv.x * ATT_SCALE), f2tf32(qv.y * ATT_SCALE),
                              f2tf32(qv.z * ATT_SCALE), f2tf32(qv.w * ATT_SCALE));
        *(uint4*)&sm[row * KSTR + c4] = uq;
    }
    __syncthreads();

    unsigned qf[8][4];
    {
        int r0 = wid * 16 + g;
#pragma unroll
        for (int kk = 0; kk < 8; kk++) {
            qf[kk][0] = sm[(r0)     * KSTR + kk * 8 + t];
            qf[kk][1] = sm[(r0 + 8) * KSTR + kk * 8 + t];
            qf[kk][2] = sm[(r0)     * KSTR + kk * 8 + t + 4];
            qf[kk][3] = sm[(r0 + 8) * KSTR + kk * 8 + t + 4];
        }
    }

    float oacc[8][4];
#pragma unroll
    for (int nt = 0; nt < 8; nt++)
#pragma unroll
        for (int r = 0; r < 4; r++) oacc[nt][r] = 0.f;

    float m0 = -1e30f, m1 = -1e30f, l0 = 0.f, l1 = 0.f;

    const unsigned FULL = 0xffffffffu;
    const int srcA = (lane & ~3) | (t >> 1);
    const int srcB = srcA + 2;

    for (int kt = 0; kt < SEQ / FTK; kt++) {
        __syncthreads();
        // Load K/V tiles [64][64] -> smem tf32. 1024 float4 each, 4/thread.
#pragma unroll
        for (int it = 0; it < 4; it++) {
            int slot = tid + 256 * it;     // 0..1023
            int row  = slot >> 4;
            int c4   = (slot & 15) * 4;
            float4 kv = *(const float4*)(kbase + (size_t)(kt * FTK + row) * DHEAD + c4);
            *(uint4*)&Ks[row * KSTR + c4] =
                make_uint4(f2tf32(kv.x), f2tf32(kv.y), f2tf32(kv.z), f2tf32(kv.w));
            float4 vv = *(const float4*)(vbase + (size_t)(kt * FTK + row) * DHEAD + c4);
            *(uint4*)&Vs[row * VSTR + c4] =
                make_uint4(f2tf32(vv.x), f2tf32(vv.y), f2tf32(vv.z), f2tf32(vv.w));
        }
        __syncthreads();

        // ---- S = Q K^T (scaled)
        float s[8][4];
#pragma unroll
        for (int nt = 0; nt < 8; nt++)
#pragma unroll
            for (int r = 0; r < 4; r++) s[nt][r] = 0.f;

#pragma unroll
        for (int kk = 0; kk < 8; kk++) {
#pragma unroll
            for (int nt = 0; nt < 8; nt++) {
                unsigned b0 = Ks[(nt * 8 + g) * KSTR + kk * 8 + t];
                unsigned b1 = Ks[(nt * 8 + g) * KSTR + kk * 8 + t + 4];
                mma_tf32(s[nt], qf[kk], b0, b1);
            }
        }

        // ---- online softmax on fragments
        float tm0 = -1e30f, tm1 = -1e30f;
#pragma unroll
        for (int nt = 0; nt < 8; nt++) {
            tm0 = fmaxf(tm0, fmaxf(s[nt][0], s[nt][1]));
            tm1 = fmaxf(tm1, fmaxf(s[nt][2], s[nt][3]));
        }
        tm0 = fmaxf(tm0, __shfl_xor_sync(FULL, tm0, 1));
        tm0 = fmaxf(tm0, __shfl_xor_sync(FULL, tm0, 2));
        tm1 = fmaxf(tm1, __shfl_xor_sync(FULL, tm1, 1));
        tm1 = fmaxf(tm1, __shfl_xor_sync(FULL, tm1, 2));

        float mn0 = fmaxf(m0, tm0), mn1 = fmaxf(m1, tm1);
        float corr0 = __expf(m0 - mn0), corr1 = __expf(m1 - mn1);
        m0 = mn0; m1 = mn1;

        float sum0 = 0.f, sum1 = 0.f;
#pragma unroll
        for (int nt = 0; nt < 8; nt++) {
            s[nt][0] = __expf(s[nt][0] - mn0);
            s[nt][1] = __expf(s[nt][1] - mn0);
            s[nt][2] = __expf(s[nt][2] - mn1);
            s[nt][3] = __expf(s[nt][3] - mn1);
            sum0 += s[nt][0] + s[nt][1];
            sum1 += s[nt][2] + s[nt][3];
        }
        sum0 += __shfl_xor_sync(FULL, sum0, 1);
        sum0 += __shfl_xor_sync(FULL, sum0, 2);
        sum1 += __shfl_xor_sync(FULL, sum1, 1);
        sum1 += __shfl_xor_sync(FULL, sum1, 2);
        l0 = l0 * corr0 + sum0;
        l1 = l1 * corr1 + sum1;

#pragma unroll
        for (int nt = 0; nt < 8; nt++) {
            oacc[nt][0] *= corr0; oacc[nt][1] *= corr0;
            oacc[nt][2] *= corr1; oacc[nt][3] *= corr1;
        }

        // ---- O += P V : A frag built from s via shfl
#pragma unroll
        for (int kk = 0; kk < 8; kk++) {
            float e, o_;
            e  = __shfl_sync(FULL, s[kk][0], srcA);
            o_ = __shfl_sync(FULL, s[kk][1], srcA);
            float p0 = (t & 1) ? o_ : e;
            e  = __shfl_sync(FULL, s[kk][2], srcA);
            o_ = __shfl_sync(FULL, s[kk][3], srcA);
            float p1 = (t & 1) ? o_ : e;
            e  = __shfl_sync(FULL, s[kk][0], srcB);
            o_ = __shfl_sync(FULL, s[kk][1], srcB);
            float p2 = (t & 1) ? o_ : e;
            e  = __shfl_sync(FULL, s[kk][2], srcB);
            o_ = __shfl_sync(FULL, s[kk][3], srcB);
            float p3 = (t & 1) ? o_ : e;
            unsigned pa[4] = {f2tf32(p0), f2tf32(p1), f2tf32(p2), f2tf32(p3)};
#pragma unroll
            for (int nt = 0; nt < 8; nt++) {
                unsigned b0 = Vs[(kk * 8 + t)     * VSTR + nt * 8 + g];
                unsigned b1 = Vs[(kk * 8 + t + 4) * VSTR + nt * 8 + g];
                mma_tf32(oacc[nt], pa, b0, b1);
            }
        }
    }

    // ---- epilogue: normalize, write ctx[b][s][h*64+d]
    float inv0 = 1.f / l0, inv1 = 1.f / l1;
    int r0 = s0 + wid * 16 + g;
#pragma unroll
    for (int nt = 0; nt < 8; nt++) {
        int col = h * DHEAD + nt * 8 + 2 * t;
        float2 w0 = make_float2(oacc[nt][0] * inv0, oacc[nt][1] * inv0);
        float2 w1 = make_float2(oacc[nt][2] * inv1, oacc[nt][3] * inv1);
        *(float2*)(ctx + (size_t)(b * SEQ + r0) * DMODEL + col)     = w0;
        *(float2*)(ctx + (size_t)(b * SEQ + r0 + 8) * DMODEL + col) = w1;
    }
}

// ---------------------------------------------------------------------------
// Launch
// ---------------------------------------------------------------------------
extern "C" void kernel_launch(void* const* d_in, const int* in_sizes, int n_in,
                              void* d_out, int out_size)
{
    (void)in_sizes; (void)n_in; (void)out_size;
    const float* x      = (const float*)d_in[0];   // [4,2048,1024]
    const int*   p      = (const int*)  d_in[1];   // [4,2048]
    const float* Wqkv_w = (const float*)d_in[2];   // [3072,1024]
    const float* Wqkv_b = (const float*)d_in[3];   // [3072]
    const float* Wo_w   = (const float*)d_in[4];   // [1024,1024]
    const float* Wo_b   = (const float*)d_in[5];   // [1024]
    float* out = (float*)d_out;                    // [4,2048,1024]

    float *qkv, *q, *k, *v, *ctx;
    cudaGetSymbolAddress((void**)&qkv, g_qkv);
    cudaGetSymbolAddress((void**)&q,   g_q);
    cudaGetSymbolAddress((void**)&k,   g_k);
    cudaGetSymbolAddress((void**)&v,   g_v);
    cudaGetSymbolAddress((void**)&ctx, g_ctx);

    const int gemm_smem = 2 * GBUFW * 4;   // 61440 B
    cudaFuncSetAttribute(tf32gemm_v3,
                         cudaFuncAttributeMaxDynamicSharedMemorySize, gemm_smem);

    // 1) QKV projection (tf32 tensor cores)
    {
        dim3 grid(N_QKV / TBN, MROWS / TBM);   // 24 x 32
        tf32gemm_v3<<<grid, 256, gemm_smem>>>(x, Wqkv_w, Wqkv_b, qkv,
                                              MROWS, N_QKV, DMODEL);
    }
    // 2) RoPE + split into [B,H,S,Dh]
    {
        int total = BATCH * NHEAD * SEQ * 32;
        rope_split_kernel<<<(total + 255) / 256, 256>>>(qkv, p, q, k, v);
    }
    // 3) Tensor-core flash attention -> ctx in [B,S,D]
    {
        dim3 grid(SEQ / FTQ, BATCH * NHEAD);   // 16 x 64
        flash_attn_tc_kernel<<<grid, 256>>>(q, k, v, ctx);
    }
    // 4) Output projection (tf32 tensor cores)
    {
        dim3 grid(DMODEL / TBN, MROWS / TBM);  // 8 x 32
        tf32gemm_v3<<<grid, 256, gemm_smem>>>(ctx, Wo_w, Wo_b, out,
                                              MROWS, DMODEL, DMODEL);
    }
}

// round 11
// speedup vs baseline: 1.4530x; 1.0837x over previous
#include <cuda_runtime.h>
#include <cuda_bf16.h>
#include <cuda_fp16.h>
#include <math.h>

// Problem constants
#define BATCH   4
#define SEQ     2048
#define DMODEL  1024
#define NHEAD   16
#define DHEAD   64
#define MROWS   (BATCH * SEQ)          // 8192
#define N_QKV   (3 * DMODEL)           // 3072
#define ATT_SCALE 0.125f               // 64^-0.5 (exact power of two)

// ---------------------------------------------------------------------------
// Device scratch (allocation-free rule: __device__ globals)
// ---------------------------------------------------------------------------
__device__ float  g_qkv[(size_t)MROWS * N_QKV];                 // 96 MB
__device__ float  g_q[(size_t)BATCH * NHEAD * SEQ * DHEAD];     // 32 MB
__device__ float  g_k[(size_t)BATCH * NHEAD * SEQ * DHEAD];     // 32 MB
__device__ __half g_vh[(size_t)BATCH * NHEAD * SEQ * DHEAD];    // 16 MB  [bh][s][d]
__device__ __half g_vt[(size_t)BATCH * NHEAD * SEQ * DHEAD];    // 16 MB  [bh][d][s]
__device__ float  g_ctx[(size_t)MROWS * DMODEL];                // 32 MB

__device__ __forceinline__ unsigned f2tf32(float f) {
    unsigned u;
    asm("cvt.rna.tf32.f32 %0, %1;" : "=r"(u) : "f"(f));
    return u;
}
__device__ __forceinline__ void mma_tf32(float* c, const unsigned* a,
                                         unsigned b0, unsigned b1) {
    asm("mma.sync.aligned.m16n8k8.row.col.f32.tf32.tf32.f32 "
        "{%0,%1,%2,%3}, {%4,%5,%6,%7}, {%8,%9}, {%0,%1,%2,%3};"
        : "+f"(c[0]), "+f"(c[1]), "+f"(c[2]), "+f"(c[3])
        : "r"(a[0]), "r"(a[1]), "r"(a[2]), "r"(a[3]), "r"(b0), "r"(b1));
}
__device__ __forceinline__ void mma_f16(float* c, const unsigned* a,
                                        unsigned b0, unsigned b1) {
    asm("mma.sync.aligned.m16n8k16.row.col.f32.f16.f16.f32 "
        "{%0,%1,%2,%3}, {%4,%5,%6,%7}, {%8,%9}, {%0,%1,%2,%3};"
        : "+f"(c[0]), "+f"(c[1]), "+f"(c[2]), "+f"(c[3])
        : "r"(a[0]), "r"(a[1]), "r"(a[2]), "r"(a[3]), "r"(b0), "r"(b1));
}
__device__ __forceinline__ unsigned f2h2(float lo, float hi) {
    __half2 h = __floats2half2_rn(lo, hi);
    return *(unsigned*)&h;
}

// ---------------------------------------------------------------------------
// TF32 tensor-core GEMM v3 (NT): unchanged from R8 (known-good).
// ---------------------------------------------------------------------------
#define TBM 256
#define TBN 128
#define TBK 16
#define SMPW 20
#define GBUFW ((TBM + TBN) * SMPW)

__global__ __launch_bounds__(256, 1)
void tf32gemm_v3(const float* __restrict__ A, const float* __restrict__ B,
                 const float* __restrict__ bias, float* __restrict__ C,
                 int M, int N, int K)
{
    extern __shared__ unsigned sm3[];

    const int tid  = threadIdx.x;
    const int lane = tid & 31;
    const int wid  = tid >> 5;
    const int wm   = wid >> 1;
    const int wn   = wid & 1;
    const int g    = lane >> 2;
    const int t    = lane & 3;

    const int bm = blockIdx.y * TBM;
    const int bn = blockIdx.x * TBN;
    const int nk = K / TBK;

    const int ldr = tid >> 2;
    const int ldc = (tid & 3) * 4;

    float acc[4][8][4];
#pragma unroll
    for (int mt = 0; mt < 4; mt++)
#pragma unroll
        for (int nt = 0; nt < 8; nt++)
#pragma unroll
            for (int r = 0; r < 4; r++) acc[mt][nt][r] = 0.f;

    float4 stA[4], stB[2];
    auto ldg = [&](int i) {
#pragma unroll
        for (int it = 0; it < 4; it++) {
            int row = ldr + 64 * it;
            stA[it] = *(const float4*)(A + (size_t)(bm + row) * K + i * TBK + ldc);
        }
#pragma unroll
        for (int it = 0; it < 2; it++) {
            int row = ldr + 64 * it;
            stB[it] = *(const float4*)(B + (size_t)(bn + row) * K + i * TBK + ldc);
        }
    };
    auto sts = [&](int i) {
        unsigned* s = sm3 + (i & 1) * GBUFW;
#pragma unroll
        for (int it = 0; it < 4; it++) {
            int row = ldr + 64 * it;
            *(uint4*)&s[row * SMPW + ldc] =
                make_uint4(f2tf32(stA[it].x), f2tf32(stA[it].y),
                           f2tf32(stA[it].z), f2tf32(stA[it].w));
        }
#pragma unroll
        for (int it = 0; it < 2; it++) {
            int row = ldr + 64 * it;
            *(uint4*)&s[TBM * SMPW + row * SMPW + ldc] =
                make_uint4(f2tf32(stB[it].x), f2tf32(stB[it].y),
                           f2tf32(stB[it].z), f2tf32(stB[it].w));
        }
    };

    ldg(0); sts(0);
    __syncthreads();

    for (int i = 0; i < nk; i++) {
        if (i + 1 < nk) ldg(i + 1);

        const unsigned* As = sm3 + (i & 1) * GBUFW;
        const unsigned* Bs = As + TBM * SMPW;
#pragma unroll
        for (int kk = 0; kk < TBK; kk += 8) {
            unsigned af[4][4], bf[8][2];
#pragma unroll
            for (int mt = 0; mt < 4; mt++) {
                int m0 = wm * 64 + mt * 16;
                af[mt][0] = As[(m0 + g)     * SMPW + kk + t];
                af[mt][1] = As[(m0 + g + 8) * SMPW + kk + t];
                af[mt][2] = As[(m0 + g)     * SMPW + kk + t + 4];
                af[mt][3] = As[(m0 + g + 8) * SMPW + kk + t + 4];
            }
#pragma unroll
            for (int nt = 0; nt < 8; nt++) {
                int n0 = wn * 64 + nt * 8;
                bf[nt][0] = Bs[(n0 + g) * SMPW + kk + t];
                bf[nt][1] = Bs[(n0 + g) * SMPW + kk + t + 4];
            }
#pragma unroll
            for (int mt = 0; mt < 4; mt++)
#pragma unroll
                for (int nt = 0; nt < 8; nt++)
                    mma_tf32(acc[mt][nt], af[mt], bf[nt][0], bf[nt][1]);
        }

        if (i + 1 < nk) sts(i + 1);
        __syncthreads();
    }

#pragma unroll
    for (int mt = 0; mt < 4; mt++) {
        int row0 = bm + wm * 64 + mt * 16 + g;
#pragma unroll
        for (int nt = 0; nt < 8; nt++) {
            int col = bn + wn * 64 + nt * 8 + 2 * t;
            float bx = bias[col], by = bias[col + 1];
            float2 r0 = make_float2(acc[mt][nt][0] + bx, acc[mt][nt][1] + by);
            float2 r1 = make_float2(acc[mt][nt][2] + bx, acc[mt][nt][3] + by);
            *(float2*)(C + (size_t)row0 * N + col)       = r0;
            *(float2*)(C + (size_t)(row0 + 8) * N + col) = r1;
        }
    }
}

// ---------------------------------------------------------------------------
// RoPE + split: qkv[M,3072] -> q,k (roped, fp32 [bh][s][d]), v (fp16 [bh][s][d]).
// ---------------------------------------------------------------------------
__global__ void rope_split_kernel(const float* __restrict__ qkv,
                                  const int* __restrict__ p,
                                  float* __restrict__ q,
                                  float* __restrict__ k,
                                  __half* __restrict__ vh)
{
    int t = blockIdx.x * blockDim.x + threadIdx.x;
    const int total = BATCH * NHEAD * SEQ * 32;
    if (t >= total) return;
    int i = t & 31;
    int s = (t >> 5) & (SEQ - 1);
    int h = (t >> 16) & (NHEAD - 1);
    int b = t >> 20;

    int m = b * SEQ + s;
    const float* row = qkv + (size_t)m * N_QKV;
    int col = h * DHEAD + i;
    float qa = row[col],            qb = row[col + 32];
    float ka = row[DMODEL + col],   kb = row[DMODEL + col + 32];
    float va = row[2*DMODEL + col], vb = row[2*DMODEL + col + 32];

    float pos = (float)p[m];
    float f = (float)exp2(-(double)i * (13.287712379549449 / 32.0)); // log2(10000)
    float ang = pos * f;
    float sn, cs;
    sincosf(ang, &sn, &cs);

    size_t o = ((size_t)(b * NHEAD + h) * SEQ + s) * DHEAD + i;
    q[o]      = qa * cs + qb * sn;
    q[o + 32] = qb * cs - qa * sn;
    k[o]      = ka * cs + kb * sn;
    k[o + 32] = kb * cs - ka * sn;
    vh[o]      = __float2half_rn(va);
    vh[o + 32] = __float2half_rn(vb);
}

// ---------------------------------------------------------------------------
// V transpose: [bh][s][64] fp16 -> [bh][64][2048] fp16, 64x64 smem tiles.
// ---------------------------------------------------------------------------
__global__ __launch_bounds__(256)
void v_transpose_kernel(const __half* __restrict__ in, __half* __restrict__ out)
{
    __shared__ __half ts[64][72];
    const int tid = threadIdx.x;
    const int s0 = blockIdx.x * 64;
    const int bh = blockIdx.y;

    const __half* ib = in + (size_t)bh * SEQ * DHEAD;
#pragma unroll
    for (int it = 0; it < 4; it++) {
        int slot = tid + 256 * it;        // 0..1023
        int r  = slot >> 4;               // s row 0..63
        int d0 = (slot & 15) * 4;         // 4 halfs
        uint2 v = *(const uint2*)(ib + (size_t)(s0 + r) * DHEAD + d0);
        *(uint2*)&ts[r][d0] = v;
    }
    __syncthreads();

    __half* ob = out + (size_t)bh * DHEAD * SEQ;
#pragma unroll
    for (int it = 0; it < 4; it++) {
        int slot = tid + 256 * it;
        int d  = slot >> 4;               // 0..63
        int s4 = (slot & 15) * 4;
        __half h0 = ts[s4 + 0][d], h1 = ts[s4 + 1][d];
        __half h2 = ts[s4 + 2][d], h3 = ts[s4 + 3][d];
        __half2 lo = __halves2half2(h0, h1), hi = __halves2half2(h2, h3);
        uint2 w = make_uint2(*(unsigned*)&lo, *(unsigned*)&hi);
        *(uint2*)(ob + (size_t)d * SEQ + s0 + s4) = w;
    }
}

// ---------------------------------------------------------------------------
// Tensor-core flash attention: QK^T in tf32 m16n8k8, P*V in fp16 m16n8k16.
// S accumulator layout == f16 A-operand layout -> no shuffles for PV.
// V consumed from transposed fp16 [d][s] tensor.
// ---------------------------------------------------------------------------
#define FTQ 128
#define FTK 64
#define KSTR 68
#define VSTR2 36   // uint (half2) stride of Vt rows (64 halfs + pad)

__global__ __launch_bounds__(256, 1)
void flash_attn_tc_kernel(const float* __restrict__ Q, const float* __restrict__ K,
                          const __half* __restrict__ Vt, float* __restrict__ ctx)
{
    // Union: Q staging [128][KSTR] words (8704 W) vs Ks[64][KSTR] + Vsu[64][VSTR2]
    __shared__ __align__(16) unsigned sm[FTQ * KSTR];
    unsigned* Ks  = sm;                    // [64][KSTR] tf32
    unsigned* Vsu = sm + FTK * KSTR;       // [64 d][VSTR2] half2

    const int tid  = threadIdx.x;
    const int lane = tid & 31;
    const int wid  = tid >> 5;
    const int g    = lane >> 2;
    const int t    = lane & 3;

    const int bh = blockIdx.y;
    const int b = bh >> 4, h = bh & 15;
    const int s0 = blockIdx.x * FTQ;

    const float*  qbase = Q  + (size_t)bh * SEQ * DHEAD;
    const float*  kbase = K  + (size_t)bh * SEQ * DHEAD;
    const __half* vbase = Vt + (size_t)bh * DHEAD * SEQ;   // [d][s]

    // --- Stage Q tile (scaled, rna tf32), build A frags.
#pragma unroll
    for (int it = 0; it < 8; it++) {
        int slot = tid + 256 * it;
        int row  = slot >> 4;
        int c4   = (slot & 15) * 4;
        float4 qv = *(const float4*)(qbase + (size_t)(s0 + row) * DHEAD + c4);
        uint4 uq = make_uint4(f2tf32(qv.x * ATT_SCALE), f2tf32(qv.y * ATT_SCALE),
                              f2tf32(qv.z * ATT_SCALE), f2tf32(qv.w * ATT_SCALE));
        *(uint4*)&sm[row * KSTR + c4] = uq;
    }
    __syncthreads();

    unsigned qf[8][4];
    {
        int r0 = wid * 16 + g;
#pragma unroll
        for (int kk = 0; kk < 8; kk++) {
            qf[kk][0] = sm[(r0)     * KSTR + kk * 8 + t];
            qf[kk][1] = sm[(r0 + 8) * KSTR + kk * 8 + t];
            qf[kk][2] = sm[(r0)     * KSTR + kk * 8 + t + 4];
            qf[kk][3] = sm[(r0 + 8) * KSTR + kk * 8 + t + 4];
        }
    }

    float oacc[8][4];
#pragma unroll
    for (int nt = 0; nt < 8; nt++)
#pragma unroll
        for (int r = 0; r < 4; r++) oacc[nt][r] = 0.f;

    float m0 = -1e30f, m1 = -1e30f, l0 = 0.f, l1 = 0.f;
    const unsigned FULL = 0xffffffffu;

    for (int kt = 0; kt < SEQ / FTK; kt++) {
        __syncthreads();
        // K tile [64 kv][64 dh] -> tf32; V tile [64 d][64 kv] fp16 from Vt.
#pragma unroll
        for (int it = 0; it < 4; it++) {
            int slot = tid + 256 * it;     // 0..1023
            int row  = slot >> 4;
            int c4   = (slot & 15) * 4;
            float4 kv = *(const float4*)(kbase + (size_t)(kt * FTK + row) * DHEAD + c4);
            *(uint4*)&Ks[row * KSTR + c4] =
                make_uint4(f2tf32(kv.x), f2tf32(kv.y), f2tf32(kv.z), f2tf32(kv.w));
        }
#pragma unroll
        for (int it = 0; it < 2; it++) {
            int slot = tid + 256 * it;     // 0..511
            int d    = slot >> 3;          // 0..63
            int kv0  = (slot & 7) * 8;     // 8 halfs along s
            uint4 vv = *(const uint4*)(vbase + (size_t)d * SEQ + kt * FTK + kv0);
            *(uint4*)&Vsu[d * VSTR2 + kv0 / 2] = vv;
        }
        __syncthreads();

        // ---- S = Q K^T (scaled)
        float s[8][4];
#pragma unroll
        for (int nt = 0; nt < 8; nt++)
#pragma unroll
            for (int r = 0; r < 4; r++) s[nt][r] = 0.f;

#pragma unroll
        for (int kk = 0; kk < 8; kk++) {
#pragma unroll
            for (int nt = 0; nt < 8; nt++) {
                unsigned b0 = Ks[(nt * 8 + g) * KSTR + kk * 8 + t];
                unsigned b1 = Ks[(nt * 8 + g) * KSTR + kk * 8 + t + 4];
                mma_tf32(s[nt], qf[kk], b0, b1);
            }
        }

        // ---- online softmax on fragments
        float tm0 = -1e30f, tm1 = -1e30f;
#pragma unroll
        for (int nt = 0; nt < 8; nt++) {
            tm0 = fmaxf(tm0, fmaxf(s[nt][0], s[nt][1]));
            tm1 = fmaxf(tm1, fmaxf(s[nt][2], s[nt][3]));
        }
        tm0 = fmaxf(tm0, __shfl_xor_sync(FULL, tm0, 1));
        tm0 = fmaxf(tm0, __shfl_xor_sync(FULL, tm0, 2));
        tm1 = fmaxf(tm1, __shfl_xor_sync(FULL, tm1, 1));
        tm1 = fmaxf(tm1, __shfl_xor_sync(FULL, tm1, 2));

        float mn0 = fmaxf(m0, tm0), mn1 = fmaxf(m1, tm1);
        float corr0 = __expf(m0 - mn0), corr1 = __expf(m1 - mn1);
        m0 = mn0; m1 = mn1;

        float sum0 = 0.f, sum1 = 0.f;
#pragma unroll
        for (int nt = 0; nt < 8; nt++) {
            s[nt][0] = __expf(s[nt][0] - mn0);
            s[nt][1] = __expf(s[nt][1] - mn0);
            s[nt][2] = __expf(s[nt][2] - mn1);
            s[nt][3] = __expf(s[nt][3] - mn1);
            sum0 += s[nt][0] + s[nt][1];
            sum1 += s[nt][2] + s[nt][3];
        }
        sum0 += __shfl_xor_sync(FULL, sum0, 1);
        sum0 += __shfl_xor_sync(FULL, sum0, 2);
        sum1 += __shfl_xor_sync(FULL, sum1, 1);
        sum1 += __shfl_xor_sync(FULL, sum1, 2);
        l0 = l0 * corr0 + sum0;
        l1 = l1 * corr1 + sum1;

#pragma unroll
        for (int nt = 0; nt < 8; nt++) {
            oacc[nt][0] *= corr0; oacc[nt][1] *= corr0;
            oacc[nt][2] *= corr1; oacc[nt][3] *= corr1;
        }

        // ---- O += P V  (fp16 m16n8k16, no shuffles: acc layout == A layout)
#pragma unroll
        for (int kk = 0; kk < 4; kk++) {
            unsigned pa[4];
            pa[0] = f2h2(s[2*kk][0],     s[2*kk][1]);
            pa[1] = f2h2(s[2*kk][2],     s[2*kk][3]);
            pa[2] = f2h2(s[2*kk + 1][0], s[2*kk + 1][1]);
            pa[3] = f2h2(s[2*kk + 1][2], s[2*kk + 1][3]);
#pragma unroll
            for (int nt = 0; nt < 8; nt++) {
                unsigned b0 = Vsu[(nt * 8 + g) * VSTR2 + kk * 8 + t];
                unsigned b1 = Vsu[(nt * 8 + g) * VSTR2 + kk * 8 + t + 4];
                mma_f16(oacc[nt], pa, b0, b1);
            }
        }
    }

    // ---- epilogue: normalize, write ctx[b][s][h*64+d]
    float inv0 = 1.f / l0, inv1 = 1.f / l1;
    int r0 = s0 + wid * 16 + g;
#pragma unroll
    for (int nt = 0; nt < 8; nt++) {
        int col = h * DHEAD + nt * 8 + 2 * t;
        float2 w0 = make_float2(oacc[nt][0] * inv0, oacc[nt][1] * inv0);
        float2 w1 = make_float2(oacc[nt][2] * inv1, oacc[nt][3] * inv1);
        *(float2*)(ctx + (size_t)(b * SEQ + r0) * DMODEL + col)     = w0;
        *(float2*)(ctx + (size_t)(b * SEQ + r0 + 8) * DMODEL + col) = w1;
    }
}

// ---------------------------------------------------------------------------
// Launch
// ---------------------------------------------------------------------------
extern "C" void kernel_launch(void* const* d_in, const int* in_sizes, int n_in,
                              void* d_out, int out_size)
{
    (void)in_sizes; (void)n_in; (void)out_size;
    const float* x      = (const float*)d_in[0];
    const int*   p      = (const int*)  d_in[1];
    const float* Wqkv_w = (const float*)d_in[2];
    const float* Wqkv_b = (const float*)d_in[3];
    const float* Wo_w   = (const float*)d_in[4];
    const float* Wo_b   = (const float*)d_in[5];
    float* out = (float*)d_out;

    float *qkv, *q, *k, *ctx;
    __half *vh, *vt;
    cudaGetSymbolAddress((void**)&qkv, g_qkv);
    cudaGetSymbolAddress((void**)&q,   g_q);
    cudaGetSymbolAddress((void**)&k,   g_k);
    cudaGetSymbolAddress((void**)&vh,  g_vh);
    cudaGetSymbolAddress((void**)&vt,  g_vt);
    cudaGetSymbolAddress((void**)&ctx, g_ctx);

    const int gemm_smem = 2 * GBUFW * 4;   // 61440 B
    cudaFuncSetAttribute(tf32gemm_v3,
                         cudaFuncAttributeMaxDynamicSharedMemorySize, gemm_smem);

    // 1) QKV projection (tf32 tensor cores)
    {
        dim3 grid(N_QKV / TBN, MROWS / TBM);   // 24 x 32
        tf32gemm_v3<<<grid, 256, gemm_smem>>>(x, Wqkv_w, Wqkv_b, qkv,
                                              MROWS, N_QKV, DMODEL);
    }
    // 2) RoPE + split (v -> fp16)
    {
        int total = BATCH * NHEAD * SEQ * 32;
        rope_split_kernel<<<(total + 255) / 256, 256>>>(qkv, p, q, k, vh);
    }
    // 2b) V transpose [bh][s][d] -> [bh][d][s]
    {
        dim3 grid(SEQ / 64, BATCH * NHEAD);    // 32 x 64
        v_transpose_kernel<<<grid, 256>>>(vh, vt);
    }
    // 3) Flash attention (tf32 QK, fp16 PV) -> ctx
    {
        dim3 grid(SEQ / FTQ, BATCH * NHEAD);   // 16 x 64
        flash_attn_tc_kernel<<<grid, 256>>>(q, k, vt, ctx);
    }
    // 4) Output projection (tf32 tensor cores)
    {
        dim3 grid(DMODEL / TBN, MROWS / TBM);  // 8 x 32
        tf32gemm_v3<<<grid, 256, gemm_smem>>>(ctx, Wo_w, Wo_b, out,
                                              MROWS, DMODEL, DMODEL);
    }
}

// round 12
// speedup vs baseline: 1.7763x; 1.2225x over previous
#include <cuda_runtime.h>
#include <cuda_bf16.h>
#include <cuda_fp16.h>
#include <math.h>

// Problem constants
#define BATCH   4
#define SEQ     2048
#define DMODEL  1024
#define NHEAD   16
#define DHEAD   64
#define MROWS   (BATCH * SEQ)          // 8192
#define N_QKV   (3 * DMODEL)           // 3072
#define ATT_SCALE 0.125f               // 64^-0.5 (exact power of two)

// ---------------------------------------------------------------------------
// Device scratch (allocation-free rule: __device__ globals)
// ---------------------------------------------------------------------------
__device__ float  g_qkv[(size_t)MROWS * N_QKV];                 // 96 MB
__device__ __half g_qh[(size_t)BATCH * NHEAD * SEQ * DHEAD];    // 16 MB [bh][s][d], pre-scaled
__device__ __half g_kh[(size_t)BATCH * NHEAD * SEQ * DHEAD];    // 16 MB [bh][s][d]
__device__ __half g_vh[(size_t)BATCH * NHEAD * SEQ * DHEAD];    // 16 MB [bh][s][d]
__device__ __half g_vt[(size_t)BATCH * NHEAD * SEQ * DHEAD];    // 16 MB [bh][d][s]
__device__ float  g_ctx[(size_t)MROWS * DMODEL];                // 32 MB

__device__ __forceinline__ unsigned f2tf32(float f) {
    unsigned u;
    asm("cvt.rna.tf32.f32 %0, %1;" : "=r"(u) : "f"(f));
    return u;
}
__device__ __forceinline__ void mma_tf32(float* c, const unsigned* a,
                                         unsigned b0, unsigned b1) {
    asm("mma.sync.aligned.m16n8k8.row.col.f32.tf32.tf32.f32 "
        "{%0,%1,%2,%3}, {%4,%5,%6,%7}, {%8,%9}, {%0,%1,%2,%3};"
        : "+f"(c[0]), "+f"(c[1]), "+f"(c[2]), "+f"(c[3])
        : "r"(a[0]), "r"(a[1]), "r"(a[2]), "r"(a[3]), "r"(b0), "r"(b1));
}
__device__ __forceinline__ void mma_f16(float* c, const unsigned* a,
                                        unsigned b0, unsigned b1) {
    asm("mma.sync.aligned.m16n8k16.row.col.f32.f16.f16.f32 "
        "{%0,%1,%2,%3}, {%4,%5,%6,%7}, {%8,%9}, {%0,%1,%2,%3};"
        : "+f"(c[0]), "+f"(c[1]), "+f"(c[2]), "+f"(c[3])
        : "r"(a[0]), "r"(a[1]), "r"(a[2]), "r"(a[3]), "r"(b0), "r"(b1));
}
__device__ __forceinline__ unsigned f2h2(float lo, float hi) {
    __half2 h = __floats2half2_rn(lo, hi);
    return *(unsigned*)&h;
}

// ---------------------------------------------------------------------------
// TF32 tensor-core GEMM v3 (NT): unchanged from R8 (known-good).
// ---------------------------------------------------------------------------
#define TBM 256
#define TBN 128
#define TBK 16
#define SMPW 20
#define GBUFW ((TBM + TBN) * SMPW)

__global__ __launch_bounds__(256, 1)
void tf32gemm_v3(const float* __restrict__ A, const float* __restrict__ B,
                 const float* __restrict__ bias, float* __restrict__ C,
                 int M, int N, int K)
{
    extern __shared__ unsigned sm3[];

    const int tid  = threadIdx.x;
    const int lane = tid & 31;
    const int wid  = tid >> 5;
    const int wm   = wid >> 1;
    const int wn   = wid & 1;
    const int g    = lane >> 2;
    const int t    = lane & 3;

    const int bm = blockIdx.y * TBM;
    const int bn = blockIdx.x * TBN;
    const int nk = K / TBK;

    const int ldr = tid >> 2;
    const int ldc = (tid & 3) * 4;

    float acc[4][8][4];
#pragma unroll
    for (int mt = 0; mt < 4; mt++)
#pragma unroll
        for (int nt = 0; nt < 8; nt++)
#pragma unroll
            for (int r = 0; r < 4; r++) acc[mt][nt][r] = 0.f;

    float4 stA[4], stB[2];
    auto ldg = [&](int i) {
#pragma unroll
        for (int it = 0; it < 4; it++) {
            int row = ldr + 64 * it;
            stA[it] = *(const float4*)(A + (size_t)(bm + row) * K + i * TBK + ldc);
        }
#pragma unroll
        for (int it = 0; it < 2; it++) {
            int row = ldr + 64 * it;
            stB[it] = *(const float4*)(B + (size_t)(bn + row) * K + i * TBK + ldc);
        }
    };
    auto sts = [&](int i) {
        unsigned* s = sm3 + (i & 1) * GBUFW;
#pragma unroll
        for (int it = 0; it < 4; it++) {
            int row = ldr + 64 * it;
            *(uint4*)&s[row * SMPW + ldc] =
                make_uint4(f2tf32(stA[it].x), f2tf32(stA[it].y),
                           f2tf32(stA[it].z), f2tf32(stA[it].w));
        }
#pragma unroll
        for (int it = 0; it < 2; it++) {
            int row = ldr + 64 * it;
            *(uint4*)&s[TBM * SMPW + row * SMPW + ldc] =
                make_uint4(f2tf32(stB[it].x), f2tf32(stB[it].y),
                           f2tf32(stB[it].z), f2tf32(stB[it].w));
        }
    };

    ldg(0); sts(0);
    __syncthreads();

    for (int i = 0; i < nk; i++) {
        if (i + 1 < nk) ldg(i + 1);

        const unsigned* As = sm3 + (i & 1) * GBUFW;
        const unsigned* Bs = As + TBM * SMPW;
#pragma unroll
        for (int kk = 0; kk < TBK; kk += 8) {
            unsigned af[4][4], bf[8][2];
#pragma unroll
            for (int mt = 0; mt < 4; mt++) {
                int m0 = wm * 64 + mt * 16;
                af[mt][0] = As[(m0 + g)     * SMPW + kk + t];
                af[mt][1] = As[(m0 + g + 8) * SMPW + kk + t];
                af[mt][2] = As[(m0 + g)     * SMPW + kk + t + 4];
                af[mt][3] = As[(m0 + g + 8) * SMPW + kk + t + 4];
            }
#pragma unroll
            for (int nt = 0; nt < 8; nt++) {
                int n0 = wn * 64 + nt * 8;
                bf[nt][0] = Bs[(n0 + g) * SMPW + kk + t];
                bf[nt][1] = Bs[(n0 + g) * SMPW + kk + t + 4];
            }
#pragma unroll
            for (int mt = 0; mt < 4; mt++)
#pragma unroll
                for (int nt = 0; nt < 8; nt++)
                    mma_tf32(acc[mt][nt], af[mt], bf[nt][0], bf[nt][1]);
        }

        if (i + 1 < nk) sts(i + 1);
        __syncthreads();
    }

#pragma unroll
    for (int mt = 0; mt < 4; mt++) {
        int row0 = bm + wm * 64 + mt * 16 + g;
#pragma unroll
        for (int nt = 0; nt < 8; nt++) {
            int col = bn + wn * 64 + nt * 8 + 2 * t;
            float bx = bias[col], by = bias[col + 1];
            float2 r0 = make_float2(acc[mt][nt][0] + bx, acc[mt][nt][1] + by);
            float2 r1 = make_float2(acc[mt][nt][2] + bx, acc[mt][nt][3] + by);
            *(float2*)(C + (size_t)row0 * N + col)       = r0;
            *(float2*)(C + (size_t)(row0 + 8) * N + col) = r1;
        }
    }
}

// ---------------------------------------------------------------------------
// RoPE + split: qkv[M,3072] -> q (roped, scaled, fp16), k (roped, fp16),
// v (fp16), all [bh][s][d].
// ---------------------------------------------------------------------------
__global__ void rope_split_kernel(const float* __restrict__ qkv,
                                  const int* __restrict__ p,
                                  __half* __restrict__ qh,
                                  __half* __restrict__ kh,
                                  __half* __restrict__ vh)
{
    int t = blockIdx.x * blockDim.x + threadIdx.x;
    const int total = BATCH * NHEAD * SEQ * 32;
    if (t >= total) return;
    int i = t & 31;
    int s = (t >> 5) & (SEQ - 1);
    int h = (t >> 16) & (NHEAD - 1);
    int b = t >> 20;

    int m = b * SEQ + s;
    const float* row = qkv + (size_t)m * N_QKV;
    int col = h * DHEAD + i;
    float qa = row[col],            qb = row[col + 32];
    float ka = row[DMODEL + col],   kb = row[DMODEL + col + 32];
    float va = row[2*DMODEL + col], vb = row[2*DMODEL + col + 32];

    float pos = (float)p[m];
    float f = (float)exp2(-(double)i * (13.287712379549449 / 32.0)); // log2(10000)
    float ang = pos * f;
    float sn, cs;
    sincosf(ang, &sn, &cs);

    size_t o = ((size_t)(b * NHEAD + h) * SEQ + s) * DHEAD + i;
    qh[o]      = __float2half_rn((qa * cs + qb * sn) * ATT_SCALE);
    qh[o + 32] = __float2half_rn((qb * cs - qa * sn) * ATT_SCALE);
    kh[o]      = __float2half_rn(ka * cs + kb * sn);
    kh[o + 32] = __float2half_rn(kb * cs - ka * sn);
    vh[o]      = __float2half_rn(va);
    vh[o + 32] = __float2half_rn(vb);
}

// ---------------------------------------------------------------------------
// V transpose: [bh][s][64] fp16 -> [bh][64][2048] fp16, 64x64 smem tiles.
// ---------------------------------------------------------------------------
__global__ __launch_bounds__(256)
void v_transpose_kernel(const __half* __restrict__ in, __half* __restrict__ out)
{
    __shared__ __half ts[64][72];
    const int tid = threadIdx.x;
    const int s0 = blockIdx.x * 64;
    const int bh = blockIdx.y;

    const __half* ib = in + (size_t)bh * SEQ * DHEAD;
#pragma unroll
    for (int it = 0; it < 4; it++) {
        int slot = tid + 256 * it;        // 0..1023
        int r  = slot >> 4;               // s row 0..63
        int d0 = (slot & 15) * 4;         // 4 halfs
        uint2 v = *(const uint2*)(ib + (size_t)(s0 + r) * DHEAD + d0);
        *(uint2*)&ts[r][d0] = v;
    }
    __syncthreads();

    __half* ob = out + (size_t)bh * DHEAD * SEQ;
#pragma unroll
    for (int it = 0; it < 4; it++) {
        int slot = tid + 256 * it;
        int d  = slot >> 4;               // 0..63
        int s4 = (slot & 15) * 4;
        __half h0 = ts[s4 + 0][d], h1 = ts[s4 + 1][d];
        __half h2 = ts[s4 + 2][d], h3 = ts[s4 + 3][d];
        __half2 lo = __halves2half2(h0, h1), hi = __halves2half2(h2, h3);
        uint2 w = make_uint2(*(unsigned*)&lo, *(unsigned*)&hi);
        *(uint2*)(ob + (size_t)d * SEQ + s0 + s4) = w;
    }
}

// ---------------------------------------------------------------------------
// Tensor-core flash attention — all-fp16 operands (m16n8k16), fp32 accum.
// 256 thr / 8 warps; TQ=128, TK=64; 2 CTAs/SM. Q pre-scaled by rope kernel.
// Smem: Q staging [128][72] halves unions with K[64][72] + V[64][72] halves.
// Row stride 36 half2 words -> fragment LDS banks 4g+t (conflict-free).
// ---------------------------------------------------------------------------
#define FTQ 128
#define FTK 64
#define HSTR 72    // halves per row
#define WSTR 36    // half2 words per row

__global__ __launch_bounds__(256, 2)
void flash_attn_tc_kernel(const __half* __restrict__ Qh, const __half* __restrict__ Kh,
                          const __half* __restrict__ Vt, float* __restrict__ ctx)
{
    __shared__ __align__(16) __half smh[FTQ * HSTR];   // 18432 B
    unsigned* Qsu = (unsigned*)smh;                     // staging view
    unsigned* Ksu = (unsigned*)smh;                     // [64][WSTR]
    unsigned* Vsu = (unsigned*)(smh + FTK * HSTR);      // [64][WSTR]

    const int tid  = threadIdx.x;
    const int lane = tid & 31;
    const int wid  = tid >> 5;
    const int g    = lane >> 2;
    const int t    = lane & 3;

    const int bh = blockIdx.y;
    const int b = bh >> 4, h = bh & 15;
    const int s0 = blockIdx.x * FTQ;

    const __half* qbase = Qh + (size_t)bh * SEQ * DHEAD;
    const __half* kbase = Kh + (size_t)bh * SEQ * DHEAD;
    const __half* vbase = Vt + (size_t)bh * DHEAD * SEQ;   // [d][s]

    // --- Stage Q tile [128][64] halves, build fp16 A frags (4 k-steps).
#pragma unroll
    for (int it = 0; it < 4; it++) {
        int slot = tid + 256 * it;       // 0..1023
        int row  = slot >> 3;            // 0..127
        int c8   = (slot & 7) * 8;       // 8 halves
        uint4 qv = *(const uint4*)(qbase + (size_t)(s0 + row) * DHEAD + c8);
        *(uint4*)&smh[row * HSTR + c8] = qv;
    }
    __syncthreads();

    unsigned qf[4][4];
    {
        int r0 = wid * 16 + g;
#pragma unroll
        for (int kk = 0; kk < 4; kk++) {
            qf[kk][0] = Qsu[(r0)     * WSTR + kk * 8 + t];
            qf[kk][1] = Qsu[(r0 + 8) * WSTR + kk * 8 + t];
            qf[kk][2] = Qsu[(r0)     * WSTR + kk * 8 + t + 4];
            qf[kk][3] = Qsu[(r0 + 8) * WSTR + kk * 8 + t + 4];
        }
    }
    __syncthreads();

    float oacc[8][4];
#pragma unroll
    for (int nt = 0; nt < 8; nt++)
#pragma unroll
        for (int r = 0; r < 4; r++) oacc[nt][r] = 0.f;

    float m0 = -1e30f, m1 = -1e30f, l0 = 0.f, l1 = 0.f;
    const unsigned FULL = 0xffffffffu;

    for (int kt = 0; kt < SEQ / FTK; kt++) {
        __syncthreads();
        // K tile [64 kv][64 d] halves; V tile [64 d][64 kv] halves.
#pragma unroll
        for (int it = 0; it < 2; it++) {
            int slot = tid + 256 * it;     // 0..511
            int row  = slot >> 3;          // 0..63
            int c8   = (slot & 7) * 8;
            uint4 kv = *(const uint4*)(kbase + (size_t)(kt * FTK + row) * DHEAD + c8);
            *(uint4*)&Ksu[row * WSTR + c8 / 2] = kv;
            uint4 vv = *(const uint4*)(vbase + (size_t)row * SEQ + kt * FTK + c8);
            *(uint4*)&Vsu[row * WSTR + c8 / 2] = vv;
        }
        __syncthreads();

        // ---- S = Q K^T (Q pre-scaled): 4 k-steps x 8 ntiles, fp16 k16
        float s[8][4];
#pragma unroll
        for (int nt = 0; nt < 8; nt++)
#pragma unroll
            for (int r = 0; r < 4; r++) s[nt][r] = 0.f;

#pragma unroll
        for (int kk = 0; kk < 4; kk++) {
#pragma unroll
            for (int nt = 0; nt < 8; nt++) {
                unsigned b0 = Ksu[(nt * 8 + g) * WSTR + kk * 8 + t];
                unsigned b1 = Ksu[(nt * 8 + g) * WSTR + kk * 8 + t + 4];
                mma_f16(s[nt], qf[kk], b0, b1);
            }
        }

        // ---- online softmax on fragments
        float tm0 = -1e30f, tm1 = -1e30f;
#pragma unroll
        for (int nt = 0; nt < 8; nt++) {
            tm0 = fmaxf(tm0, fmaxf(s[nt][0], s[nt][1]));
            tm1 = fmaxf(tm1, fmaxf(s[nt][2], s[nt][3]));
        }
        tm0 = fmaxf(tm0, __shfl_xor_sync(FULL, tm0, 1));
        tm0 = fmaxf(tm0, __shfl_xor_sync(FULL, tm0, 2));
        tm1 = fmaxf(tm1, __shfl_xor_sync(FULL, tm1, 1));
        tm1 = fmaxf(tm1, __shfl_xor_sync(FULL, tm1, 2));

        float mn0 = fmaxf(m0, tm0), mn1 = fmaxf(m1, tm1);
        float corr0 = __expf(m0 - mn0), corr1 = __expf(m1 - mn1);
        m0 = mn0; m1 = mn1;

        float sum0 = 0.f, sum1 = 0.f;
#pragma unroll
        for (int nt = 0; nt < 8; nt++) {
            s[nt][0] = __expf(s[nt][0] - mn0);
            s[nt][1] = __expf(s[nt][1] - mn0);
            s[nt][2] = __expf(s[nt][2] - mn1);
            s[nt][3] = __expf(s[nt][3] - mn1);
            sum0 += s[nt][0] + s[nt][1];
            sum1 += s[nt][2] + s[nt][3];
        }
        sum0 += __shfl_xor_sync(FULL, sum0, 1);
        sum0 += __shfl_xor_sync(FULL, sum0, 2);
        sum1 += __shfl_xor_sync(FULL, sum1, 1);
        sum1 += __shfl_xor_sync(FULL, sum1, 2);
        l0 = l0 * corr0 + sum0;
        l1 = l1 * corr1 + sum1;

#pragma unroll
        for (int nt = 0; nt < 8; nt++) {
            oacc[nt][0] *= corr0; oacc[nt][1] *= corr0;
            oacc[nt][2] *= corr1; oacc[nt][3] *= corr1;
        }

        // ---- O += P V  (fp16 k16, acc layout == A layout: no shuffles)
#pragma unroll
        for (int kk = 0; kk < 4; kk++) {
            unsigned pa[4];
            pa[0] = f2h2(s[2*kk][0],     s[2*kk][1]);
            pa[1] = f2h2(s[2*kk][2],     s[2*kk][3]);
            pa[2] = f2h2(s[2*kk + 1][0], s[2*kk + 1][1]);
            pa[3] = f2h2(s[2*kk + 1][2], s[2*kk + 1][3]);
#pragma unroll
            for (int nt = 0; nt < 8; nt++) {
                unsigned b0 = Vsu[(nt * 8 + g) * WSTR + kk * 8 + t];
                unsigned b1 = Vsu[(nt * 8 + g) * WSTR + kk * 8 + t + 4];
                mma_f16(oacc[nt], pa, b0, b1);
            }
        }
    }

    // ---- epilogue: normalize, write ctx[b][s][h*64+d]
    float inv0 = 1.f / l0, inv1 = 1.f / l1;
    int r0 = s0 + wid * 16 + g;
#pragma unroll
    for (int nt = 0; nt < 8; nt++) {
        int col = h * DHEAD + nt * 8 + 2 * t;
        float2 w0 = make_float2(oacc[nt][0] * inv0, oacc[nt][1] * inv0);
        float2 w1 = make_float2(oacc[nt][2] * inv1, oacc[nt][3] * inv1);
        *(float2*)(ctx + (size_t)(b * SEQ + r0) * DMODEL + col)     = w0;
        *(float2*)(ctx + (size_t)(b * SEQ + r0 + 8) * DMODEL + col) = w1;
    }
}

// ---------------------------------------------------------------------------
// Launch
// ---------------------------------------------------------------------------
extern "C" void kernel_launch(void* const* d_in, const int* in_sizes, int n_in,
                              void* d_out, int out_size)
{
    (void)in_sizes; (void)n_in; (void)out_size;
    const float* x      = (const float*)d_in[0];
    const int*   p      = (const int*)  d_in[1];
    const float* Wqkv_w = (const float*)d_in[2];
    const float* Wqkv_b = (const float*)d_in[3];
    const float* Wo_w   = (const float*)d_in[4];
    const float* Wo_b   = (const float*)d_in[5];
    float* out = (float*)d_out;

    float *qkv, *ctx;
    __half *qh, *kh, *vh, *vt;
    cudaGetSymbolAddress((void**)&qkv, g_qkv);
    cudaGetSymbolAddress((void**)&qh,  g_qh);
    cudaGetSymbolAddress((void**)&kh,  g_kh);
    cudaGetSymbolAddress((void**)&vh,  g_vh);
    cudaGetSymbolAddress((void**)&vt,  g_vt);
    cudaGetSymbolAddress((void**)&ctx, g_ctx);

    const int gemm_smem = 2 * GBUFW * 4;   // 61440 B
    cudaFuncSetAttribute(tf32gemm_v3,
                         cudaFuncAttributeMaxDynamicSharedMemorySize, gemm_smem);

    // 1) QKV projection (tf32 tensor cores)
    {
        dim3 grid(N_QKV / TBN, MROWS / TBM);   // 24 x 32
        tf32gemm_v3<<<grid, 256, gemm_smem>>>(x, Wqkv_w, Wqkv_b, qkv,
                                              MROWS, N_QKV, DMODEL);
    }
    // 2) RoPE + split -> fp16 q (scaled), k, v
    {
        int total = BATCH * NHEAD * SEQ * 32;
        rope_split_kernel<<<(total + 255) / 256, 256>>>(qkv, p, qh, kh, vh);
    }
    // 2b) V transpose [bh][s][d] -> [bh][d][s]
    {
        dim3 grid(SEQ / 64, BATCH * NHEAD);    // 32 x 64
        v_transpose_kernel<<<grid, 256>>>(vh, vt);
    }
    // 3) Flash attention (all-fp16 MMA) -> ctx
    {
        dim3 grid(SEQ / FTQ, BATCH * NHEAD);   // 16 x 64
        flash_attn_tc_kernel<<<grid, 256>>>(qh, kh, vt, ctx);
    }
    // 4) Output projection (tf32 tensor cores)
    {
        dim3 grid(DMODEL / TBN, MROWS / TBM);  // 8 x 32
        tf32gemm_v3<<<grid, 256, gemm_smem>>>(ctx, Wo_w, Wo_b, out,
                                              MROWS, DMODEL, DMODEL);
    }
}

// round 14
// speedup vs baseline: 2.3723x; 1.3355x over previous
#include <cuda_runtime.h>
#include <cuda_bf16.h>
#include <cuda_fp16.h>
#include <math.h>

// Problem constants
#define BATCH   4
#define SEQ     2048
#define DMODEL  1024
#define NHEAD   16
#define DHEAD   64
#define MROWS   (BATCH * SEQ)          // 8192
#define N_QKV   (3 * DMODEL)           // 3072
#define ATT_SCALE 0.125f               // 64^-0.5 (exact power of two)

// ---------------------------------------------------------------------------
// Device scratch (allocation-free rule: __device__ globals)
// ---------------------------------------------------------------------------
__device__ float  g_qkv[(size_t)MROWS * N_QKV];                 // 96 MB
__device__ __half g_qh[(size_t)BATCH * NHEAD * SEQ * DHEAD];    // 16 MB [bh][s][d], pre-scaled
__device__ __half g_kh[(size_t)BATCH * NHEAD * SEQ * DHEAD];    // 16 MB [bh][s][d]
__device__ __half g_vh[(size_t)BATCH * NHEAD * SEQ * DHEAD];    // 16 MB [bh][s][d]
__device__ __half g_vt[(size_t)BATCH * NHEAD * SEQ * DHEAD];    // 16 MB [bh][d][s]
__device__ float  g_ctx[(size_t)MROWS * DMODEL];                // 32 MB

__device__ __forceinline__ void mma_f16(float* c, const unsigned* a,
                                        unsigned b0, unsigned b1) {
    asm("mma.sync.aligned.m16n8k16.row.col.f32.f16.f16.f32 "
        "{%0,%1,%2,%3}, {%4,%5,%6,%7}, {%8,%9}, {%0,%1,%2,%3};"
        : "+f"(c[0]), "+f"(c[1]), "+f"(c[2]), "+f"(c[3])
        : "r"(a[0]), "r"(a[1]), "r"(a[2]), "r"(a[3]), "r"(b0), "r"(b1));
}
__device__ __forceinline__ unsigned f2h2(float lo, float hi) {
    __half2 h = __floats2half2_rn(lo, hi);
    return *(unsigned*)&h;
}

// ---------------------------------------------------------------------------
// FP16 tensor-core GEMM v4 (NT): C[m,n] = sum_k A[m,k]*B[n,k] + bias[n]
// fp32 in/out, fp16 operands (rn convert), fp32 accumulate.
// Block tile 256x128, TBK=32 halves (2 x k16 steps), 256 thr / 8 warps,
// warp tile 64x64. Double-buffered smem + register-staged LDG prefetch.
// Row stride 20 half2-words -> fragment banks (20g+t)%32: full bijection.
// ---------------------------------------------------------------------------
#define TBM 256
#define TBN 128
#define TBK 32                            // halves per k-iter
#define SMPW2 20                          // half2 words per row
#define GBUFW2 ((TBM + TBN) * SMPW2)      // 7680 words per buffer

__global__ __launch_bounds__(256, 1)
void hgemm_v4(const float* __restrict__ A, const float* __restrict__ B,
              const float* __restrict__ bias, float* __restrict__ C,
              int M, int N, int K)
{
    extern __shared__ unsigned sm4[];

    const int tid  = threadIdx.x;
    const int lane = tid & 31;
    const int wid  = tid >> 5;
    const int wm   = wid >> 1;            // 0..3 -> 64 rows
    const int wn   = wid & 1;             // 0..1 -> 64 cols
    const int g    = lane >> 2;           // 0..7
    const int t    = lane & 3;            // 0..3

    const int bm = blockIdx.y * TBM;
    const int bn = blockIdx.x * TBN;
    const int nk = K / TBK;

    const int ldr = tid >> 2;             // 0..63
    const int ldc = (tid & 3) * 8;        // half offset 0,8,16,24

    float acc[4][8][4];
#pragma unroll
    for (int mt = 0; mt < 4; mt++)
#pragma unroll
        for (int nt = 0; nt < 8; nt++)
#pragma unroll
            for (int r = 0; r < 4; r++) acc[mt][nt][r] = 0.f;

    float4 stA[4][2], stB[2][2];
    auto ldg = [&](int i) {
#pragma unroll
        for (int it = 0; it < 4; it++) {
            int row = ldr + 64 * it;      // 0..255
            const float* src = A + (size_t)(bm + row) * K + i * TBK + ldc;
            stA[it][0] = *(const float4*)src;
            stA[it][1] = *(const float4*)(src + 4);
        }
#pragma unroll
        for (int it = 0; it < 2; it++) {
            int row = ldr + 64 * it;      // 0..127
            const float* src = B + (size_t)(bn + row) * K + i * TBK + ldc;
            stB[it][0] = *(const float4*)src;
            stB[it][1] = *(const float4*)(src + 4);
        }
    };
    auto sts = [&](int i) {
        unsigned* s = sm4 + (i & 1) * GBUFW2;
#pragma unroll
        for (int it = 0; it < 4; it++) {
            int row = ldr + 64 * it;
            *(uint4*)&s[row * SMPW2 + ldc / 2] = make_uint4(
                f2h2(stA[it][0].x, stA[it][0].y), f2h2(stA[it][0].z, stA[it][0].w),
                f2h2(stA[it][1].x, stA[it][1].y), f2h2(stA[it][1].z, stA[it][1].w));
        }
#pragma unroll
        for (int it = 0; it < 2; it++) {
            int row = ldr + 64 * it;
            *(uint4*)&s[TBM * SMPW2 + row * SMPW2 + ldc / 2] = make_uint4(
                f2h2(stB[it][0].x, stB[it][0].y), f2h2(stB[it][0].z, stB[it][0].w),
                f2h2(stB[it][1].x, stB[it][1].y), f2h2(stB[it][1].z, stB[it][1].w));
        }
    };

    ldg(0); sts(0);
    __syncthreads();

    for (int i = 0; i < nk; i++) {
        if (i + 1 < nk) ldg(i + 1);

        const unsigned* As = sm4 + (i & 1) * GBUFW2;
        const unsigned* Bs = As + TBM * SMPW2;
#pragma unroll
        for (int kk = 0; kk < 2; kk++) {           // 2 x k16 steps
            unsigned af[4][4], bf[8][2];
#pragma unroll
            for (int mt = 0; mt < 4; mt++) {
                int m0 = wm * 64 + mt * 16;
                af[mt][0] = As[(m0 + g)     * SMPW2 + kk * 8 + t];
                af[mt][1] = As[(m0 + g + 8) * SMPW2 + kk * 8 + t];
                af[mt][2] = As[(m0 + g)     * SMPW2 + kk * 8 + t + 4];
                af[mt][3] = As[(m0 + g + 8) * SMPW2 + kk * 8 + t + 4];
            }
#pragma unroll
            for (int nt = 0; nt < 8; nt++) {
                int n0 = wn * 64 + nt * 8;
                bf[nt][0] = Bs[(n0 + g) * SMPW2 + kk * 8 + t];
                bf[nt][1] = Bs[(n0 + g) * SMPW2 + kk * 8 + t + 4];
            }
#pragma unroll
            for (int mt = 0; mt < 4; mt++)
#pragma unroll
                for (int nt = 0; nt < 8; nt++)
                    mma_f16(acc[mt][nt], af[mt], bf[nt][0], bf[nt][1]);
        }

        if (i + 1 < nk) sts(i + 1);
        __syncthreads();
    }

    // Epilogue: bias + float2 stores.
#pragma unroll
    for (int mt = 0; mt < 4; mt++) {
        int row0 = bm + wm * 64 + mt * 16 + g;
#pragma unroll
        for (int nt = 0; nt < 8; nt++) {
            int col = bn + wn * 64 + nt * 8 + 2 * t;
            float bx = bias[col], by = bias[col + 1];
            float2 r0 = make_float2(acc[mt][nt][0] + bx, acc[mt][nt][1] + by);
            float2 r1 = make_float2(acc[mt][nt][2] + bx, acc[mt][nt][3] + by);
            *(float2*)(C + (size_t)row0 * N + col)       = r0;
            *(float2*)(C + (size_t)(row0 + 8) * N + col) = r1;
        }
    }
}

// ---------------------------------------------------------------------------
// RoPE + split: qkv[M,3072] -> q (roped, scaled, fp16), k (roped, fp16),
// v (fp16), all [bh][s][d].
// ---------------------------------------------------------------------------
__global__ void rope_split_kernel(const float* __restrict__ qkv,
                                  const int* __restrict__ p,
                                  __half* __restrict__ qh,
                                  __half* __restrict__ kh,
                                  __half* __restrict__ vh)
{
    int t = blockIdx.x * blockDim.x + threadIdx.x;
    const int total = BATCH * NHEAD * SEQ * 32;
    if (t >= total) return;
    int i = t & 31;
    int s = (t >> 5) & (SEQ - 1);
    int h = (t >> 16) & (NHEAD - 1);
    int b = t >> 20;

    int m = b * SEQ + s;
    const float* row = qkv + (size_t)m * N_QKV;
    int col = h * DHEAD + i;
    float qa = row[col],            qb = row[col + 32];
    float ka = row[DMODEL + col],   kb = row[DMODEL + col + 32];
    float va = row[2*DMODEL + col], vb = row[2*DMODEL + col + 32];

    float pos = (float)p[m];
    float f = (float)exp2(-(double)i * (13.287712379549449 / 32.0)); // log2(10000)
    float ang = pos * f;
    float sn, cs;
    sincosf(ang, &sn, &cs);

    size_t o = ((size_t)(b * NHEAD + h) * SEQ + s) * DHEAD + i;
    qh[o]      = __float2half_rn((qa * cs + qb * sn) * ATT_SCALE);
    qh[o + 32] = __float2half_rn((qb * cs - qa * sn) * ATT_SCALE);
    kh[o]      = __float2half_rn(ka * cs + kb * sn);
    kh[o + 32] = __float2half_rn(kb * cs - ka * sn);
    vh[o]      = __float2half_rn(va);
    vh[o + 32] = __float2half_rn(vb);
}

// ---------------------------------------------------------------------------
// V transpose: [bh][s][64] fp16 -> [bh][64][2048] fp16, 64x64 smem tiles.
// ---------------------------------------------------------------------------
__global__ __launch_bounds__(256)
void v_transpose_kernel(const __half* __restrict__ in, __half* __restrict__ out)
{
    __shared__ __half ts[64][72];
    const int tid = threadIdx.x;
    const int s0 = blockIdx.x * 64;
    const int bh = blockIdx.y;

    const __half* ib = in + (size_t)bh * SEQ * DHEAD;
#pragma unroll
    for (int it = 0; it < 4; it++) {
        int slot = tid + 256 * it;        // 0..1023
        int r  = slot >> 4;               // s row 0..63
        int d0 = (slot & 15) * 4;         // 4 halfs
        uint2 v = *(const uint2*)(ib + (size_t)(s0 + r) * DHEAD + d0);
        *(uint2*)&ts[r][d0] = v;
    }
    __syncthreads();

    __half* ob = out + (size_t)bh * DHEAD * SEQ;
#pragma unroll
    for (int it = 0; it < 4; it++) {
        int slot = tid + 256 * it;
        int d  = slot >> 4;               // 0..63
        int s4 = (slot & 15) * 4;
        __half h0 = ts[s4 + 0][d], h1 = ts[s4 + 1][d];
        __half h2 = ts[s4 + 2][d], h3 = ts[s4 + 3][d];
        __half2 lo = __halves2half2(h0, h1), hi = __halves2half2(h2, h3);
        uint2 w = make_uint2(*(unsigned*)&lo, *(unsigned*)&hi);
        *(uint2*)(ob + (size_t)d * SEQ + s0 + s4) = w;
    }
}

// ---------------------------------------------------------------------------
// Tensor-core flash attention — all-fp16 operands (m16n8k16), fp32 accum.
// Unchanged from R12 (known-good): 256 thr / 8 warps; TQ=128, TK=64; 2 CTAs/SM.
// ---------------------------------------------------------------------------
#define FTQ 128
#define FTK 64
#define HSTR 72    // halves per row
#define WSTR 36    // half2 words per row

__global__ __launch_bounds__(256, 2)
void flash_attn_tc_kernel(const __half* __restrict__ Qh, const __half* __restrict__ Kh,
                          const __half* __restrict__ Vt, float* __restrict__ ctx)
{
    __shared__ __align__(16) __half smh[FTQ * HSTR];   // 18432 B
    unsigned* Qsu = (unsigned*)smh;                     // staging view
    unsigned* Ksu = (unsigned*)smh;                     // [64][WSTR]
    unsigned* Vsu = (unsigned*)(smh + FTK * HSTR);      // [64][WSTR]

    const int tid  = threadIdx.x;
    const int lane = tid & 31;
    const int wid  = tid >> 5;
    const int g    = lane >> 2;
    const int t    = lane & 3;

    const int bh = blockIdx.y;
    const int b = bh >> 4, h = bh & 15;
    const int s0 = blockIdx.x * FTQ;

    const __half* qbase = Qh + (size_t)bh * SEQ * DHEAD;
    const __half* kbase = Kh + (size_t)bh * SEQ * DHEAD;
    const __half* vbase = Vt + (size_t)bh * DHEAD * SEQ;   // [d][s]

    // --- Stage Q tile [128][64] halves, build fp16 A frags (4 k-steps).
#pragma unroll
    for (int it = 0; it < 4; it++) {
        int slot = tid + 256 * it;       // 0..1023
        int row  = slot >> 3;            // 0..127
        int c8   = (slot & 7) * 8;       // 8 halves
        uint4 qv = *(const uint4*)(qbase + (size_t)(s0 + row) * DHEAD + c8);
        *(uint4*)&smh[row * HSTR + c8] = qv;
    }
    __syncthreads();

    unsigned qf[4][4];
    {
        int r0 = wid * 16 + g;
#pragma unroll
        for (int kk = 0; kk < 4; kk++) {
            qf[kk][0] = Qsu[(r0)     * WSTR + kk * 8 + t];
            qf[kk][1] = Qsu[(r0 + 8) * WSTR + kk * 8 + t];
            qf[kk][2] = Qsu[(r0)     * WSTR + kk * 8 + t + 4];
            qf[kk][3] = Qsu[(r0 + 8) * WSTR + kk * 8 + t + 4];
        }
    }
    __syncthreads();

    float oacc[8][4];
#pragma unroll
    for (int nt = 0; nt < 8; nt++)
#pragma unroll
        for (int r = 0; r < 4; r++) oacc[nt][r] = 0.f;

    float m0 = -1e30f, m1 = -1e30f, l0 = 0.f, l1 = 0.f;
    const unsigned FULL = 0xffffffffu;

    for (int kt = 0; kt < SEQ / FTK; kt++) {
        __syncthreads();
        // K tile [64 kv][64 d] halves; V tile [64 d][64 kv] halves.
#pragma unroll
        for (int it = 0; it < 2; it++) {
            int slot = tid + 256 * it;     // 0..511
            int row  = slot >> 3;          // 0..63
            int c8   = (slot & 7) * 8;
            uint4 kv = *(const uint4*)(kbase + (size_t)(kt * FTK + row) * DHEAD + c8);
            *(uint4*)&Ksu[row * WSTR + c8 / 2] = kv;
            uint4 vv = *(const uint4*)(vbase + (size_t)row * SEQ + kt * FTK + c8);
            *(uint4*)&Vsu[row * WSTR + c8 / 2] = vv;
        }
        __syncthreads();

        // ---- S = Q K^T (Q pre-scaled): 4 k-steps x 8 ntiles, fp16 k16
        float s[8][4];
#pragma unroll
        for (int nt = 0; nt < 8; nt++)
#pragma unroll
            for (int r = 0; r < 4; r++) s[nt][r] = 0.f;

#pragma unroll
        for (int kk = 0; kk < 4; kk++) {
#pragma unroll
            for (int nt = 0; nt < 8; nt++) {
                unsigned b0 = Ksu[(nt * 8 + g) * WSTR + kk * 8 + t];
                unsigned b1 = Ksu[(nt * 8 + g) * WSTR + kk * 8 + t + 4];
                mma_f16(s[nt], qf[kk], b0, b1);
            }
        }

        // ---- online softmax on fragments
        float tm0 = -1e30f, tm1 = -1e30f;
#pragma unroll
        for (int nt = 0; nt < 8; nt++) {
            tm0 = fmaxf(tm0, fmaxf(s[nt][0], s[nt][1]));
            tm1 = fmaxf(tm1, fmaxf(s[nt][2], s[nt][3]));
        }
        tm0 = fmaxf(tm0, __shfl_xor_sync(FULL, tm0, 1));
        tm0 = fmaxf(tm0, __shfl_xor_sync(FULL, tm0, 2));
        tm1 = fmaxf(tm1, __shfl_xor_sync(FULL, tm1, 1));
        tm1 = fmaxf(tm1, __shfl_xor_sync(FULL, tm1, 2));

        float mn0 = fmaxf(m0, tm0), mn1 = fmaxf(m1, tm1);
        float corr0 = __expf(m0 - mn0), corr1 = __expf(m1 - mn1);
        m0 = mn0; m1 = mn1;

        float sum0 = 0.f, sum1 = 0.f;
#pragma unroll
        for (int nt = 0; nt < 8; nt++) {
            s[nt][0] = __expf(s[nt][0] - mn0);
            s[nt][1] = __expf(s[nt][1] - mn0);
            s[nt][2] = __expf(s[nt][2] - mn1);
            s[nt][3] = __expf(s[nt][3] - mn1);
            sum0 += s[nt][0] + s[nt][1];
            sum1 += s[nt][2] + s[nt][3];
        }
        sum0 += __shfl_xor_sync(FULL, sum0, 1);
        sum0 += __shfl_xor_sync(FULL, sum0, 2);
        sum1 += __shfl_xor_sync(FULL, sum1, 1);
        sum1 += __shfl_xor_sync(FULL, sum1, 2);
        l0 = l0 * corr0 + sum0;
        l1 = l1 * corr1 + sum1;

#pragma unroll
        for (int nt = 0; nt < 8; nt++) {
            oacc[nt][0] *= corr0; oacc[nt][1] *= corr0;
            oacc[nt][2] *= corr1; oacc[nt][3] *= corr1;
        }

        // ---- O += P V  (fp16 k16, acc layout == A layout: no shuffles)
#pragma unroll
        for (int kk = 0; kk < 4; kk++) {
            unsigned pa[4];
            pa[0] = f2h2(s[2*kk][0],     s[2*kk][1]);
            pa[1] = f2h2(s[2*kk][2],     s[2*kk][3]);
            pa[2] = f2h2(s[2*kk + 1][0], s[2*kk + 1][1]);
            pa[3] = f2h2(s[2*kk + 1][2], s[2*kk + 1][3]);
#pragma unroll
            for (int nt = 0; nt < 8; nt++) {
                unsigned b0 = Vsu[(nt * 8 + g) * WSTR + kk * 8 + t];
                unsigned b1 = Vsu[(nt * 8 + g) * WSTR + kk * 8 + t + 4];
                mma_f16(oacc[nt], pa, b0, b1);
            }
        }
    }

    // ---- epilogue: normalize, write ctx[b][s][h*64+d]
    float inv0 = 1.f / l0, inv1 = 1.f / l1;
    int r0 = s0 + wid * 16 + g;
#pragma unroll
    for (int nt = 0; nt < 8; nt++) {
        int col = h * DHEAD + nt * 8 + 2 * t;
        float2 w0 = make_float2(oacc[nt][0] * inv0, oacc[nt][1] * inv0);
        float2 w1 = make_float2(oacc[nt][2] * inv1, oacc[nt][3] * inv1);
        *(float2*)(ctx + (size_t)(b * SEQ + r0) * DMODEL + col)     = w0;
        *(float2*)(ctx + (size_t)(b * SEQ + r0 + 8) * DMODEL + col) = w1;
    }
}

// ---------------------------------------------------------------------------
// Launch
// ---------------------------------------------------------------------------
extern "C" void kernel_launch(void* const* d_in, const int* in_sizes, int n_in,
                              void* d_out, int out_size)
{
    (void)in_sizes; (void)n_in; (void)out_size;
    const float* x      = (const float*)d_in[0];
    const int*   p      = (const int*)  d_in[1];
    const float* Wqkv_w = (const float*)d_in[2];
    const float* Wqkv_b = (const float*)d_in[3];
    const float* Wo_w   = (const float*)d_in[4];
    const float* Wo_b   = (const float*)d_in[5];
    float* out = (float*)d_out;

    float *qkv, *ctx;
    __half *qh, *kh, *vh, *vt;
    cudaGetSymbolAddress((void**)&qkv, g_qkv);
    cudaGetSymbolAddress((void**)&qh,  g_qh);
    cudaGetSymbolAddress((void**)&kh,  g_kh);
    cudaGetSymbolAddress((void**)&vh,  g_vh);
    cudaGetSymbolAddress((void**)&vt,  g_vt);
    cudaGetSymbolAddress((void**)&ctx, g_ctx);

    const int gemm_smem = 2 * GBUFW2 * 4;   // 61440 B
    cudaFuncSetAttribute(hgemm_v4,
                         cudaFuncAttributeMaxDynamicSharedMemorySize, gemm_smem);

    // 1) QKV projection (fp16 tensor cores, fp32 accumulate)
    {
        dim3 grid(N_QKV / TBN, MROWS / TBM);   // 24 x 32
        hgemm_v4<<<grid, 256, gemm_smem>>>(x, Wqkv_w, Wqkv_b, qkv,
                                           MROWS, N_QKV, DMODEL);
    }
    // 2) RoPE + split -> fp16 q (scaled), k, v
    {
        int total = BATCH * NHEAD * SEQ * 32;
        rope_split_kernel<<<(total + 255) / 256, 256>>>(qkv, p, qh, kh, vh);
    }
    // 2b) V transpose [bh][s][d] -> [bh][d][s]
    {
        dim3 grid(SEQ / 64, BATCH * NHEAD);    // 32 x 64
        v_transpose_kernel<<<grid, 256>>>(vh, vt);
    }
    // 3) Flash attention (all-fp16 MMA) -> ctx
    {
        dim3 grid(SEQ / FTQ, BATCH * NHEAD);   // 16 x 64
        flash_attn_tc_kernel<<<grid, 256>>>(qh, kh, vt, ctx);
    }
    // 4) Output projection (fp16 tensor cores, fp32 accumulate)
    {
        dim3 grid(DMODEL / TBN, MROWS / TBM);  // 8 x 32
        hgemm_v4<<<grid, 256, gemm_smem>>>(ctx, Wo_w, Wo_b, out,
                                           MROWS, DMODEL, DMODEL);
    }
}

// round 15
// speedup vs baseline: 2.9658x; 1.2502x over previous
#include <cuda_runtime.h>
#include <cuda_bf16.h>
#include <cuda_fp16.h>
#include <math.h>

// Problem constants
#define BATCH   4
#define SEQ     2048
#define DMODEL  1024
#define NHEAD   16
#define DHEAD   64
#define MROWS   (BATCH * SEQ)          // 8192
#define N_QKV   (3 * DMODEL)           // 3072
// Q pre-scale: 64^-0.5 * log2(e)  (base-2 softmax)
#define QSCALE  0.1803368801111204f

// ---------------------------------------------------------------------------
// Device scratch (allocation-free rule: __device__ globals)
// ---------------------------------------------------------------------------
__device__ __half g_qh[(size_t)BATCH * NHEAD * SEQ * DHEAD];    // [bh][s][d], pre-scaled
__device__ __half g_kh[(size_t)BATCH * NHEAD * SEQ * DHEAD];    // [bh][s][d]
__device__ __half g_vh[(size_t)BATCH * NHEAD * SEQ * DHEAD];    // [bh][s][d]
__device__ __half g_vt[(size_t)BATCH * NHEAD * SEQ * DHEAD];    // [bh][d][s]
__device__ float  g_ctx[(size_t)MROWS * DMODEL];                // [m][1024]
__device__ float2 g_cs[(size_t)MROWS * 32];                     // [m][i] {cos,sin}, 2 MB

__device__ __forceinline__ void mma_f16(float* c, const unsigned* a,
                                        unsigned b0, unsigned b1) {
    asm("mma.sync.aligned.m16n8k16.row.col.f32.f16.f16.f32 "
        "{%0,%1,%2,%3}, {%4,%5,%6,%7}, {%8,%9}, {%0,%1,%2,%3};"
        : "+f"(c[0]), "+f"(c[1]), "+f"(c[2]), "+f"(c[3])
        : "r"(a[0]), "r"(a[1]), "r"(a[2]), "r"(a[3]), "r"(b0), "r"(b1));
}
__device__ __forceinline__ unsigned f2h2(float lo, float hi) {
    __half2 h = __floats2half2_rn(lo, hi);
    return *(unsigned*)&h;
}
__device__ __forceinline__ float ex2(float x) {
    float y;
    asm("ex2.approx.ftz.f32 %0, %1;" : "=f"(y) : "f"(x));
    return y;
}

// ---------------------------------------------------------------------------
// Cos/sin table: g_cs[m][i] = {cos(p[m]*f_i), sin(p[m]*f_i)}, i in [0,32).
// ---------------------------------------------------------------------------
__global__ void cs_table_kernel(const int* __restrict__ p, float2* __restrict__ cs)
{
    int idx = blockIdx.x * blockDim.x + threadIdx.x;
    if (idx >= MROWS * 32) return;
    int m = idx >> 5, i = idx & 31;
    float f = (float)exp2(-(double)i * (13.287712379549449 / 32.0)); // log2(10000)
    float ang = (float)p[m] * f;
    float sn, c;
    sincosf(ang, &sn, &c);
    cs[idx] = make_float2(c, sn);
}

// ---------------------------------------------------------------------------
// Shared GEMM tiling constants (256x128 block, TBK=32 halves, 8 warps 64x64).
// Row stride 20 half2-words -> fragment banks (20g+t)%32: bijection/warp.
// ---------------------------------------------------------------------------
#define TBM 256
#define TBN 128
#define TBK 32
#define SMPW2 20
#define GBUFW2 ((TBM + TBN) * SMPW2)      // 7680 words per buffer

// Mainloop shared by both GEMMs (defines acc[4][8][4] in caller scope).
#define HGEMM_MAINLOOP(A, B, K)                                                \
    const int lane = tid & 31;                                                 \
    const int wid  = tid >> 5;                                                 \
    const int wm   = wid >> 1;                                                 \
    const int wn   = wid & 1;                                                  \
    const int g    = lane >> 2;                                                \
    const int t    = lane & 3;                                                 \
    const int nk   = (K) / TBK;                                                \
    const int ldr  = tid >> 2;                                                 \
    const int ldc  = (tid & 3) * 8;                                            \
    float acc[4][8][4];                                                        \
    _Pragma("unroll")                                                          \
    for (int mt = 0; mt < 4; mt++)                                             \
        _Pragma("unroll")                                                      \
        for (int nt = 0; nt < 8; nt++)                                         \
            _Pragma("unroll")                                                  \
            for (int r = 0; r < 4; r++) acc[mt][nt][r] = 0.f;                  \
    float4 stA[4][2], stB[2][2];                                               \
    auto ldg = [&](int i) {                                                    \
        _Pragma("unroll")                                                      \
        for (int it = 0; it < 4; it++) {                                       \
            int row = ldr + 64 * it;                                           \
            const float* src = (A) + (size_t)(bm + row) * (K) + i * TBK + ldc; \
            stA[it][0] = *(const float4*)src;                                  \
            stA[it][1] = *(const float4*)(src + 4);                            \
        }                                                                      \
        _Pragma("unroll")                                                      \
        for (int it = 0; it < 2; it++) {                                       \
            int row = ldr + 64 * it;                                           \
            const float* src = (B) + (size_t)(bn + row) * (K) + i * TBK + ldc; \
            stB[it][0] = *(const float4*)src;                                  \
            stB[it][1] = *(const float4*)(src + 4);                            \
        }                                                                      \
    };                                                                         \
    auto sts = [&](int i) {                                                    \
        unsigned* s = smg + (i & 1) * GBUFW2;                                  \
        _Pragma("unroll")                                                      \
        for (int it = 0; it < 4; it++) {                                       \
            int row = ldr + 64 * it;                                           \
            *(uint4*)&s[row * SMPW2 + ldc / 2] = make_uint4(                   \
                f2h2(stA[it][0].x, stA[it][0].y), f2h2(stA[it][0].z, stA[it][0].w), \
                f2h2(stA[it][1].x, stA[it][1].y), f2h2(stA[it][1].z, stA[it][1].w)); \
        }                                                                      \
        _Pragma("unroll")                                                      \
        for (int it = 0; it < 2; it++) {                                       \
            int row = ldr + 64 * it;                                           \
            *(uint4*)&s[TBM * SMPW2 + row * SMPW2 + ldc / 2] = make_uint4(     \
                f2h2(stB[it][0].x, stB[it][0].y), f2h2(stB[it][0].z, stB[it][0].w), \
                f2h2(stB[it][1].x, stB[it][1].y), f2h2(stB[it][1].z, stB[it][1].w)); \
        }                                                                      \
    };                                                                         \
    ldg(0); sts(0);                                                            \
    __syncthreads();                                                           \
    for (int i = 0; i < nk; i++) {                                             \
        if (i + 1 < nk) ldg(i + 1);                                            \
        const unsigned* As = smg + (i & 1) * GBUFW2;                           \
        const unsigned* Bs = As + TBM * SMPW2;                                 \
        _Pragma("unroll")                                                      \
        for (int kk = 0; kk < 2; kk++) {                                       \
            unsigned af[4][4], bf[8][2];                                       \
            _Pragma("unroll")                                                  \
            for (int mt = 0; mt < 4; mt++) {                                   \
                int m0 = wm * 64 + mt * 16;                                    \
                af[mt][0] = As[(m0 + g)     * SMPW2 + kk * 8 + t];             \
                af[mt][1] = As[(m0 + g + 8) * SMPW2 + kk * 8 + t];             \
                af[mt][2] = As[(m0 + g)     * SMPW2 + kk * 8 + t + 4];         \
                af[mt][3] = As[(m0 + g + 8) * SMPW2 + kk * 8 + t + 4];         \
            }                                                                  \
            _Pragma("unroll")                                                  \
            for (int nt = 0; nt < 8; nt++) {                                   \
                int n0 = wn * 64 + nt * 8;                                     \
                bf[nt][0] = Bs[(n0 + g) * SMPW2 + kk * 8 + t];                 \
                bf[nt][1] = Bs[(n0 + g) * SMPW2 + kk * 8 + t + 4];             \
            }                                                                  \
            _Pragma("unroll")                                                  \
            for (int mt = 0; mt < 4; mt++)                                     \
                _Pragma("unroll")                                              \
                for (int nt = 0; nt < 8; nt++)                                 \
                    mma_f16(acc[mt][nt], af[mt], bf[nt][0], bf[nt][1]);        \
        }                                                                      \
        if (i + 1 < nk) sts(i + 1);                                            \
        __syncthreads();                                                       \
    }

// ---------------------------------------------------------------------------
// QKV GEMM with fused bias + RoPE + fp16 split epilogue.
// n in [0,1024): Q (roped, QSCALE) -> qh; [1024,2048): K (roped) -> kh;
// [2048,3072): V -> vh. Rope pair (i, i+32) = fragments (nt, nt+4).
// ---------------------------------------------------------------------------
__global__ __launch_bounds__(256, 1)
void hgemm_qkv_rope(const float* __restrict__ A, const float* __restrict__ B,
                    const float* __restrict__ bias, const float2* __restrict__ cs,
                    __half* __restrict__ qh, __half* __restrict__ kh,
                    __half* __restrict__ vh)
{
    extern __shared__ unsigned smg[];
    const int tid = threadIdx.x;
    const int bm = blockIdx.y * TBM;
    const int bn = blockIdx.x * TBN;

    HGEMM_MAINLOOP(A, B, DMODEL)

    // ---- fused epilogue
    const int nbase = bn + wn * 64;            // head-aligned (multiple of 64)
    const int kind  = nbase >> 10;             // 0=Q, 1=K, 2=V
    const int h     = (nbase & 1023) >> 6;
    __half* outArr = (kind == 0) ? qh : (kind == 1) ? kh : vh;

#pragma unroll
    for (int mt = 0; mt < 4; mt++) {
        int rowb = bm + wm * 64 + mt * 16 + g;
#pragma unroll
        for (int r = 0; r < 2; r++) {
            int row = rowb + 8 * r;
            int b = row >> 11, s = row & (SEQ - 1);
            size_t obase = ((size_t)(b * NHEAD + h) * SEQ + s) * DHEAD;
            if (kind == 2) {
#pragma unroll
                for (int nt = 0; nt < 8; nt++) {
                    int d = nt * 8 + 2 * t;
                    float v0 = acc[mt][nt][2*r]     + bias[nbase + d];
                    float v1 = acc[mt][nt][2*r + 1] + bias[nbase + d + 1];
                    *(unsigned*)(outArr + obase + d) = f2h2(v0, v1);
                }
            } else {
                float sc = (kind == 0) ? QSCALE : 1.0f;
#pragma unroll
                for (int nt = 0; nt < 4; nt++) {
                    int i0 = nt * 8 + 2 * t;                 // 0..30, even
                    float a0 = acc[mt][nt][2*r]       + bias[nbase + i0];
                    float a1 = acc[mt][nt][2*r + 1]   + bias[nbase + i0 + 1];
                    float b0 = acc[mt][nt+4][2*r]     + bias[nbase + i0 + 32];
                    float b1 = acc[mt][nt+4][2*r + 1] + bias[nbase + i0 + 33];
                    float4 c = *(const float4*)&cs[(size_t)row * 32 + i0];
                    // c = {cos_i0, sin_i0, cos_i1, sin_i1}
                    float o0 = (a0 * c.x + b0 * c.y) * sc;
                    float o1 = (a1 * c.z + b1 * c.w) * sc;
                    float p0 = (b0 * c.x - a0 * c.y) * sc;
                    float p1 = (b1 * c.z - a1 * c.w) * sc;
                    *(unsigned*)(outArr + obase + i0)      = f2h2(o0, o1);
                    *(unsigned*)(outArr + obase + i0 + 32) = f2h2(p0, p1);
                }
            }
        }
    }
}

// ---------------------------------------------------------------------------
// Generic FP16 GEMM (NT) + bias, fp32 out — for the output projection.
// ---------------------------------------------------------------------------
__global__ __launch_bounds__(256, 1)
void hgemm_v4(const float* __restrict__ A, const float* __restrict__ B,
              const float* __restrict__ bias, float* __restrict__ C,
              int M, int N, int K)
{
    extern __shared__ unsigned smg[];
    const int tid = threadIdx.x;
    const int bm = blockIdx.y * TBM;
    const int bn = blockIdx.x * TBN;

    HGEMM_MAINLOOP(A, B, K)

#pragma unroll
    for (int mt = 0; mt < 4; mt++) {
        int row0 = bm + wm * 64 + mt * 16 + g;
#pragma unroll
        for (int nt = 0; nt < 8; nt++) {
            int col = bn + wn * 64 + nt * 8 + 2 * t;
            float bx = bias[col], by = bias[col + 1];
            float2 r0 = make_float2(acc[mt][nt][0] + bx, acc[mt][nt][1] + by);
            float2 r1 = make_float2(acc[mt][nt][2] + bx, acc[mt][nt][3] + by);
            *(float2*)(C + (size_t)row0 * N + col)       = r0;
            *(float2*)(C + (size_t)(row0 + 8) * N + col) = r1;
        }
    }
}

// ---------------------------------------------------------------------------
// V transpose: [bh][s][64] fp16 -> [bh][64][2048] fp16, 64x64 smem tiles.
// ---------------------------------------------------------------------------
__global__ __launch_bounds__(256)
void v_transpose_kernel(const __half* __restrict__ in, __half* __restrict__ out)
{
    __shared__ __half ts[64][72];
    const int tid = threadIdx.x;
    const int s0 = blockIdx.x * 64;
    const int bh = blockIdx.y;

    const __half* ib = in + (size_t)bh * SEQ * DHEAD;
#pragma unroll
    for (int it = 0; it < 4; it++) {
        int slot = tid + 256 * it;
        int r  = slot >> 4;
        int d0 = (slot & 15) * 4;
        uint2 v = *(const uint2*)(ib + (size_t)(s0 + r) * DHEAD + d0);
        *(uint2*)&ts[r][d0] = v;
    }
    __syncthreads();

    __half* ob = out + (size_t)bh * DHEAD * SEQ;
#pragma unroll
    for (int it = 0; it < 4; it++) {
        int slot = tid + 256 * it;
        int d  = slot >> 4;
        int s4 = (slot & 15) * 4;
        __half h0 = ts[s4 + 0][d], h1 = ts[s4 + 1][d];
        __half h2 = ts[s4 + 2][d], h3 = ts[s4 + 3][d];
        __half2 lo = __halves2half2(h0, h1), hi = __halves2half2(h2, h3);
        uint2 w = make_uint2(*(unsigned*)&lo, *(unsigned*)&hi);
        *(uint2*)(ob + (size_t)d * SEQ + s0 + s4) = w;
    }
}

// ---------------------------------------------------------------------------
// Tensor-core flash attention — all-fp16 operands, fp32 accum, base-2 softmax
// (Q pre-scaled by 64^-0.5 * log2(e); exp via bare ex2.approx).
// 256 thr / 8 warps; TQ=128, TK=64; 2 CTAs/SM.
// ---------------------------------------------------------------------------
#define FTQ 128
#define FTK 64
#define HSTR 72
#define WSTR 36

__global__ __launch_bounds__(256, 2)
void flash_attn_tc_kernel(const __half* __restrict__ Qh, const __half* __restrict__ Kh,
                          const __half* __restrict__ Vt, float* __restrict__ ctx)
{
    __shared__ __align__(16) __half smh[FTQ * HSTR];   // 18432 B
    unsigned* Qsu = (unsigned*)smh;
    unsigned* Ksu = (unsigned*)smh;
    unsigned* Vsu = (unsigned*)(smh + FTK * HSTR);

    const int tid  = threadIdx.x;
    const int lane = tid & 31;
    const int wid  = tid >> 5;
    const int g    = lane >> 2;
    const int t    = lane & 3;

    const int bh = blockIdx.y;
    const int b = bh >> 4, h = bh & 15;
    const int s0 = blockIdx.x * FTQ;

    const __half* qbase = Qh + (size_t)bh * SEQ * DHEAD;
    const __half* kbase = Kh + (size_t)bh * SEQ * DHEAD;
    const __half* vbase = Vt + (size_t)bh * DHEAD * SEQ;

#pragma unroll
    for (int it = 0; it < 4; it++) {
        int slot = tid + 256 * it;
        int row  = slot >> 3;
        int c8   = (slot & 7) * 8;
        uint4 qv = *(const uint4*)(qbase + (size_t)(s0 + row) * DHEAD + c8);
        *(uint4*)&smh[row * HSTR + c8] = qv;
    }
    __syncthreads();

    unsigned qf[4][4];
    {
        int r0 = wid * 16 + g;
#pragma unroll
        for (int kk = 0; kk < 4; kk++) {
            qf[kk][0] = Qsu[(r0)     * WSTR + kk * 8 + t];
            qf[kk][1] = Qsu[(r0 + 8) * WSTR + kk * 8 + t];
            qf[kk][2] = Qsu[(r0)     * WSTR + kk * 8 + t + 4];
            qf[kk][3] = Qsu[(r0 + 8) * WSTR + kk * 8 + t + 4];
        }
    }
    __syncthreads();

    float oacc[8][4];
#pragma unroll
    for (int nt = 0; nt < 8; nt++)
#pragma unroll
        for (int r = 0; r < 4; r++) oacc[nt][r] = 0.f;

    float m0 = -1e30f, m1 = -1e30f, l0 = 0.f, l1 = 0.f;
    const unsigned FULL = 0xffffffffu;

    for (int kt = 0; kt < SEQ / FTK; kt++) {
        __syncthreads();
#pragma unroll
        for (int it = 0; it < 2; it++) {
            int slot = tid + 256 * it;
            int row  = slot >> 3;
            int c8   = (slot & 7) * 8;
            uint4 kv = *(const uint4*)(kbase + (size_t)(kt * FTK + row) * DHEAD + c8);
            *(uint4*)&Ksu[row * WSTR + c8 / 2] = kv;
            uint4 vv = *(const uint4*)(vbase + (size_t)row * SEQ + kt * FTK + c8);
            *(uint4*)&Vsu[row * WSTR + c8 / 2] = vv;
        }
        __syncthreads();

        float s[8][4];
#pragma unroll
        for (int nt = 0; nt < 8; nt++)
#pragma unroll
            for (int r = 0; r < 4; r++) s[nt][r] = 0.f;

#pragma unroll
        for (int kk = 0; kk < 4; kk++) {
#pragma unroll
            for (int nt = 0; nt < 8; nt++) {
                unsigned b0 = Ksu[(nt * 8 + g) * WSTR + kk * 8 + t];
                unsigned b1 = Ksu[(nt * 8 + g) * WSTR + kk * 8 + t + 4];
                mma_f16(s[nt], qf[kk], b0, b1);
            }
        }

        // ---- online softmax (base 2)
        float tm0 = -1e30f, tm1 = -1e30f;
#pragma unroll
        for (int nt = 0; nt < 8; nt++) {
            tm0 = fmaxf(tm0, fmaxf(s[nt][0], s[nt][1]));
            tm1 = fmaxf(tm1, fmaxf(s[nt][2], s[nt][3]));
        }
        tm0 = fmaxf(tm0, __shfl_xor_sync(FULL, tm0, 1));
        tm0 = fmaxf(tm0, __shfl_xor_sync(FULL, tm0, 2));
        tm1 = fmaxf(tm1, __shfl_xor_sync(FULL, tm1, 1));
        tm1 = fmaxf(tm1, __shfl_xor_sync(FULL, tm1, 2));

        float mn0 = fmaxf(m0, tm0), mn1 = fmaxf(m1, tm1);
        float corr0 = ex2(m0 - mn0), corr1 = ex2(m1 - mn1);
        m0 = mn0; m1 = mn1;

        float sum0 = 0.f, sum1 = 0.f;
#pragma unroll
        for (int nt = 0; nt < 8; nt++) {
            s[nt][0] = ex2(s[nt][0] - mn0);
            s[nt][1] = ex2(s[nt][1] - mn0);
            s[nt][2] = ex2(s[nt][2] - mn1);
            s[nt][3] = ex2(s[nt][3] - mn1);
            sum0 += s[nt][0] + s[nt][1];
            sum1 += s[nt][2] + s[nt][3];
        }
        sum0 += __shfl_xor_sync(FULL, sum0, 1);
        sum0 += __shfl_xor_sync(FULL, sum0, 2);
        sum1 += __shfl_xor_sync(FULL, sum1, 1);
        sum1 += __shfl_xor_sync(FULL, sum1, 2);
        l0 = l0 * corr0 + sum0;
        l1 = l1 * corr1 + sum1;

#pragma unroll
        for (int nt = 0; nt < 8; nt++) {
            oacc[nt][0] *= corr0; oacc[nt][1] *= corr0;
            oacc[nt][2] *= corr1; oacc[nt][3] *= corr1;
        }

        // ---- O += P V  (fp16 k16, acc layout == A layout: no shuffles)
#pragma unroll
        for (int kk = 0; kk < 4; kk++) {
            unsigned pa[4];
            pa[0] = f2h2(s[2*kk][0],     s[2*kk][1]);
            pa[1] = f2h2(s[2*kk][2],     s[2*kk][3]);
            pa[2] = f2h2(s[2*kk + 1][0], s[2*kk + 1][1]);
            pa[3] = f2h2(s[2*kk + 1][2], s[2*kk + 1][3]);
#pragma unroll
            for (int nt = 0; nt < 8; nt++) {
                unsigned b0 = Vsu[(nt * 8 + g) * WSTR + kk * 8 + t];
                unsigned b1 = Vsu[(nt * 8 + g) * WSTR + kk * 8 + t + 4];
                mma_f16(oacc[nt], pa, b0, b1);
            }
        }
    }

    float inv0 = 1.f / l0, inv1 = 1.f / l1;
    int r0 = s0 + wid * 16 + g;
#pragma unroll
    for (int nt = 0; nt < 8; nt++) {
        int col = h * DHEAD + nt * 8 + 2 * t;
        float2 w0 = make_float2(oacc[nt][0] * inv0, oacc[nt][1] * inv0);
        float2 w1 = make_float2(oacc[nt][2] * inv1, oacc[nt][3] * inv1);
        *(float2*)(ctx + (size_t)(b * SEQ + r0) * DMODEL + col)     = w0;
        *(float2*)(ctx + (size_t)(b * SEQ + r0 + 8) * DMODEL + col) = w1;
    }
}

// ---------------------------------------------------------------------------
// Launch
// ---------------------------------------------------------------------------
extern "C" void kernel_launch(void* const* d_in, const int* in_sizes, int n_in,
                              void* d_out, int out_size)
{
    (void)in_sizes; (void)n_in; (void)out_size;
    const float* x      = (const float*)d_in[0];
    const int*   p      = (const int*)  d_in[1];
    const float* Wqkv_w = (const float*)d_in[2];
    const float* Wqkv_b = (const float*)d_in[3];
    const float* Wo_w   = (const float*)d_in[4];
    const float* Wo_b   = (const float*)d_in[5];
    float* out = (float*)d_out;

    float *ctx;
    float2 *cs;
    __half *qh, *kh, *vh, *vt;
    cudaGetSymbolAddress((void**)&qh,  g_qh);
    cudaGetSymbolAddress((void**)&kh,  g_kh);
    cudaGetSymbolAddress((void**)&vh,  g_vh);
    cudaGetSymbolAddress((void**)&vt,  g_vt);
    cudaGetSymbolAddress((void**)&ctx, g_ctx);
    cudaGetSymbolAddress((void**)&cs,  g_cs);

    const int gemm_smem = 2 * GBUFW2 * 4;   // 61440 B
    cudaFuncSetAttribute(hgemm_qkv_rope,
                         cudaFuncAttributeMaxDynamicSharedMemorySize, gemm_smem);
    cudaFuncSetAttribute(hgemm_v4,
                         cudaFuncAttributeMaxDynamicSharedMemorySize, gemm_smem);

    // 0) cos/sin table
    {
        int total = MROWS * 32;
        cs_table_kernel<<<(total + 255) / 256, 256>>>(p, cs);
    }
    // 1) QKV projection + bias + RoPE + fp16 split (fused)
    {
        dim3 grid(N_QKV / TBN, MROWS / TBM);   // 24 x 32
        hgemm_qkv_rope<<<grid, 256, gemm_smem>>>(x, Wqkv_w, Wqkv_b, cs,
                                                 qh, kh, vh);
    }
    // 2) V transpose [bh][s][d] -> [bh][d][s]
    {
        dim3 grid(SEQ / 64, BATCH * NHEAD);    // 32 x 64
        v_transpose_kernel<<<grid, 256>>>(vh, vt);
    }
    // 3) Flash attention (all-fp16 MMA, base-2 softmax) -> ctx
    {
        dim3 grid(SEQ / FTQ, BATCH * NHEAD);   // 16 x 64
        flash_attn_tc_kernel<<<grid, 256>>>(qh, kh, vt, ctx);
    }
    // 4) Output projection (fp16 tensor cores, fp32 accumulate)
    {
        dim3 grid(DMODEL / TBN, MROWS / TBM);  // 8 x 32
        hgemm_v4<<<grid, 256, gemm_smem>>>(ctx, Wo_w, Wo_b, out,
                                           MROWS, DMODEL, DMODEL);
    }
}